// round 15
// baseline (speedup 1.0000x reference)
#include <cuda_runtime.h>
#include <cuda_bf16.h>
#include <cstdint>

#define N_NODES 10000
#define E_EDGES 320000
#define HID 256
#define K_HOPS 10
#define D_RNA 2000
#define D_ATAC 5000

// ---------------- scratch (static device allocations; no cudaMalloc) -------
__device__ float g_b0[N_NODES * HID];
__device__ float g_b1[N_NODES * HID];
__device__ float g_b2[N_NODES * HID];
__device__ float g_b3[N_NODES * HID];
__device__ float g_b4[N_NODES * HID];
__device__ float g_b5[N_NODES * HID];
__device__ float g_b6[N_NODES * HID];
__device__ float g_zcr[N_NODES * 2 * HID];
__device__ float g_zca[N_NODES * 2 * HID];
__device__ float g_fw[4 * (K_HOPS + 1)];
__device__ int   g_rowptr[2 * (N_NODES + 1)];
__device__ int   g_cols[2 * E_EDGES];
__device__ float g_vals[2 * E_EDGES];
__device__ int   g_cnt[2 * N_NODES];
__device__ int   g_cur[2 * N_NODES];
// split-bf16 operand buffers
__device__ __nv_bfloat16 g_acr[(size_t)N_NODES * 6016];
__device__ __nv_bfloat16 g_aca[(size_t)N_NODES * 15008];
__device__ __nv_bfloat16 g_awor[(size_t)N_NODES * 1536];
__device__ __nv_bfloat16 g_awoa[(size_t)N_NODES * 1536];
__device__ __nv_bfloat16 g_az[(size_t)N_NODES * 768];
__device__ __nv_bfloat16 g_adr[(size_t)N_NODES * 768];
__device__ __nv_bfloat16 g_ada[(size_t)N_NODES * 768];
__device__ __nv_bfloat16 g_bwir0[6016 * 256];
__device__ __nv_bfloat16 g_bwir1[6016 * 256];
__device__ __nv_bfloat16 g_bwia0[15008 * 256];
__device__ __nv_bfloat16 g_bwia1[15008 * 256];
__device__ __nv_bfloat16 g_bwor[1536 * 256];
__device__ __nv_bfloat16 g_bwoa[1536 * 256];
__device__ __nv_bfloat16 g_bd1r[768 * 256];
__device__ __nv_bfloat16 g_bd1a[768 * 256];
__device__ __nv_bfloat16 g_bd2r[768 * 2000];
__device__ __nv_bfloat16 g_bd2a[768 * 5000];

// ================= split-bf16 conversion kernels ===========================
__global__ void conv_a(const float* __restrict__ A, __nv_bfloat16* __restrict__ out,
                       int M, int K, int Kcp)
{
    int kh = K >> 1;
    int total = M * kh;
    for (int i = blockIdx.x * blockDim.x + threadIdx.x; i < total;
         i += gridDim.x * blockDim.x) {
        int m = i / kh;
        int k = (i - m * kh) * 2;
        float2 x = *(const float2*)(A + (size_t)m * K + k);
        __nv_bfloat16 h0 = __float2bfloat16(x.x);
        __nv_bfloat16 h1 = __float2bfloat16(x.y);
        __nv_bfloat16 l0 = __float2bfloat16(x.x - __bfloat162float(h0));
        __nv_bfloat16 l1 = __float2bfloat16(x.y - __bfloat162float(h1));
        __nv_bfloat162 hp; hp.x = h0; hp.y = h1;
        __nv_bfloat162 lp; lp.x = l0; lp.y = l1;
        size_t base = (size_t)m * Kcp + k;
        *(__nv_bfloat162*)(out + base) = hp;
        *(__nv_bfloat162*)(out + base + K) = lp;
        *(__nv_bfloat162*)(out + base + 2 * K) = hp;
    }
}

__global__ void pad_a(__nv_bfloat16* out, int M, int Kcp, int start)
{
    int w = Kcp - start;
    int total = M * w;
    for (int i = blockIdx.x * blockDim.x + threadIdx.x; i < total;
         i += gridDim.x * blockDim.x) {
        int m = i / w;
        int j = i - m * w;
        out[(size_t)m * Kcp + start + j] = __float2bfloat16(0.f);
    }
}

__global__ void conv_b(const float* __restrict__ B, __nv_bfloat16* __restrict__ out,
                       int K, int N)
{
    int nh = N >> 1;
    int total = K * nh;
    for (int i = blockIdx.x * blockDim.x + threadIdx.x; i < total;
         i += gridDim.x * blockDim.x) {
        int k = i / nh;
        int n = (i - k * nh) * 2;
        float2 x = *(const float2*)(B + (size_t)k * N + n);
        __nv_bfloat16 h0 = __float2bfloat16(x.x);
        __nv_bfloat16 h1 = __float2bfloat16(x.y);
        __nv_bfloat16 l0 = __float2bfloat16(x.x - __bfloat162float(h0));
        __nv_bfloat16 l1 = __float2bfloat16(x.y - __bfloat162float(h1));
        __nv_bfloat162 hp; hp.x = h0; hp.y = h1;
        __nv_bfloat162 lp; lp.x = l0; lp.y = l1;
        *(__nv_bfloat162*)(out + (size_t)k * N + n) = hp;
        *(__nv_bfloat162*)(out + (size_t)(K + k) * N + n) = hp;
        *(__nv_bfloat162*)(out + (size_t)(2 * K + k) * N + n) = lp;
    }
}

__global__ void pad_b(__nv_bfloat16* out, int count)
{
    for (int i = blockIdx.x * blockDim.x + threadIdx.x; i < count;
         i += gridDim.x * blockDim.x)
        out[i] = __float2bfloat16(0.f);
}

// ================= bf16 tensor-core GEMM ===================================
__device__ __forceinline__ void cpa16(void* sm, const void* gm, bool p)
{
    unsigned int s = (unsigned int)__cvta_generic_to_shared(sm);
    int sz = p ? 16 : 0;
    asm volatile("cp.async.cg.shared.global [%0], [%1], 16, %2;"
                 :: "r"(s), "l"(gm), "r"(sz) : "memory");
}
__device__ __forceinline__ void ldsm4(unsigned int* d, const void* p)
{
    unsigned int s = (unsigned int)__cvta_generic_to_shared(p);
    asm volatile("ldmatrix.sync.aligned.m8n8.x4.shared.b16 {%0,%1,%2,%3}, [%4];"
                 : "=r"(d[0]), "=r"(d[1]), "=r"(d[2]), "=r"(d[3]) : "r"(s));
}
__device__ __forceinline__ void ldsm4t(unsigned int* d, const void* p)
{
    unsigned int s = (unsigned int)__cvta_generic_to_shared(p);
    asm volatile("ldmatrix.sync.aligned.m8n8.x4.trans.shared.b16 {%0,%1,%2,%3}, [%4];"
                 : "=r"(d[0]), "=r"(d[1]), "=r"(d[2]), "=r"(d[3]) : "r"(s));
}
__device__ __forceinline__ void mma16816(float* c, const unsigned int* a,
                                         unsigned int b0, unsigned int b1)
{
    asm volatile("mma.sync.aligned.m16n8k16.row.col.f32.bf16.bf16.f32 "
                 "{%0,%1,%2,%3}, {%4,%5,%6,%7}, {%8,%9}, {%0,%1,%2,%3};"
                 : "+f"(c[0]), "+f"(c[1]), "+f"(c[2]), "+f"(c[3])
                 : "r"(a[0]), "r"(a[1]), "r"(a[2]), "r"(a[3]), "r"(b0), "r"(b1));
}

__global__ __launch_bounds__(256, 2) void gemm_bf16(
    const __nv_bfloat16* __restrict__ A, const __nv_bfloat16* __restrict__ B,
    const float* __restrict__ bias, float* __restrict__ C,
    int M, int N, int Kc, int relu, int colBase)
{
    __shared__ __nv_bfloat16 As[2][128][40];
    __shared__ __nv_bfloat16 Bs[2][32][136];

    const int tid = threadIdx.x;
    const int lane = tid & 31;
    const int warp = tid >> 5;
    const int wm = warp >> 2;
    const int wn = warp & 3;
    const int row0 = blockIdx.y * 128;
    const int col0 = (blockIdx.x + colBase) * 128;

    const int ar = tid >> 1;
    const int ac = (tid & 1) << 4;
    const int arow = row0 + ar;
    const bool apred = arow < M;
    const __nv_bfloat16* Abase = A + (size_t)(apred ? arow : 0) * Kc + ac;

    const int br = tid >> 3;
    const int bc = (tid & 7) << 4;
    const int bcol = col0 + bc;
    const bool bp0 = bcol < N;
    const bool bp1 = (bcol + 8) < N;
    const int bc0 = bp0 ? bcol : 0;
    const int bc1 = bp1 ? (bcol + 8) : 0;

    float acc[4][4][4];
#pragma unroll
    for (int i = 0; i < 4; i++) {
#pragma unroll
        for (int j = 0; j < 4; j++) {
#pragma unroll
            for (int q = 0; q < 4; q++) acc[i][j][q] = 0.f;
        }
    }

    const int iters = Kc >> 5;

    cpa16(&As[0][ar][ac], Abase, apred);
    cpa16(&As[0][ar][ac + 8], Abase + 8, apred);
    {
        const __nv_bfloat16* Bb = B + (size_t)br * N;
        cpa16(&Bs[0][br][bc], Bb + bc0, bp0);
        cpa16(&Bs[0][br][bc + 8], Bb + bc1, bp1);
    }
    asm volatile("cp.async.commit_group;" ::: "memory");

    int s = 0;
    for (int it = 0; it < iters; it++) {
        if (it + 1 < iters) {
            const int kk = (it + 1) << 5;
            cpa16(&As[s ^ 1][ar][ac], Abase + kk, apred);
            cpa16(&As[s ^ 1][ar][ac + 8], Abase + kk + 8, apred);
            const __nv_bfloat16* Bb = B + (size_t)(kk + br) * N;
            cpa16(&Bs[s ^ 1][br][bc], Bb + bc0, bp0);
            cpa16(&Bs[s ^ 1][br][bc + 8], Bb + bc1, bp1);
            asm volatile("cp.async.commit_group;" ::: "memory");
            asm volatile("cp.async.wait_group 1;" ::: "memory");
        } else {
            asm volatile("cp.async.wait_group 0;" ::: "memory");
        }
        __syncthreads();

#pragma unroll
        for (int k16 = 0; k16 < 2; k16++) {
            unsigned int af[4][4];
#pragma unroll
            for (int mi = 0; mi < 4; mi++) {
                ldsm4(af[mi], &As[s][wm * 64 + mi * 16 + (lane & 15)]
                                    [k16 * 16 + ((lane >> 4) << 3)]);
            }
            unsigned int bfr[2][4];
#pragma unroll
            for (int g = 0; g < 2; g++) {
                ldsm4t(bfr[g], &Bs[s][k16 * 16 + (lane & 15)]
                                     [wn * 32 + g * 16 + ((lane >> 4) << 3)]);
            }
#pragma unroll
            for (int mi = 0; mi < 4; mi++) {
#pragma unroll
                for (int ni = 0; ni < 4; ni++) {
                    mma16816(acc[mi][ni], af[mi],
                             bfr[ni >> 1][(ni & 1) * 2],
                             bfr[ni >> 1][(ni & 1) * 2 + 1]);
                }
            }
        }
        __syncthreads();
        s ^= 1;
    }

#pragma unroll
    for (int mi = 0; mi < 4; mi++) {
        int r = row0 + wm * 64 + mi * 16 + (lane >> 2);
#pragma unroll
        for (int ni = 0; ni < 4; ni++) {
            int c = col0 + wn * 32 + ni * 8 + ((lane & 3) << 1);
            if (c < N) {
                float b0 = bias[c];
                float b1 = bias[c + 1];
                if (r < M) {
                    float o0 = acc[mi][ni][0] + b0;
                    float o1 = acc[mi][ni][1] + b1;
                    if (relu) { o0 = fmaxf(o0, 0.f); o1 = fmaxf(o1, 0.f); }
                    *(float2*)(C + (size_t)r * N + c) = make_float2(o0, o1);
                }
                if (r + 8 < M) {
                    float o2 = acc[mi][ni][2] + b0;
                    float o3 = acc[mi][ni][3] + b1;
                    if (relu) { o2 = fmaxf(o2, 0.f); o3 = fmaxf(o3, 0.f); }
                    *(float2*)(C + (size_t)(r + 8) * N + c) = make_float2(o2, o3);
                }
            }
        }
    }
}

// ================= CSR construction ========================================
__global__ void zero_cnt(int* cnt)
{
    int i = blockIdx.x * blockDim.x + threadIdx.x;
    if (i < N_NODES) cnt[i] = 0;
}
__global__ void hist_rows(const int* __restrict__ row, int* cnt)
{
    int i = blockIdx.x * blockDim.x + threadIdx.x;
    if (i < E_EDGES) atomicAdd(&cnt[row[i]], 1);
}
__global__ void exscan(const int* __restrict__ cnt, int* rowptr)
{
    __shared__ int part[256];
    int t = threadIdx.x;
    int base = t * 40;
    int s = 0;
#pragma unroll
    for (int j = 0; j < 40; j++) {
        int idx = base + j;
        if (idx < N_NODES) s += cnt[idx];
    }
    part[t] = s;
    __syncthreads();
    for (int off = 1; off < 256; off <<= 1) {
        int v = (t >= off) ? part[t - off] : 0;
        __syncthreads();
        part[t] += v;
        __syncthreads();
    }
    int run = (t > 0) ? part[t - 1] : 0;
#pragma unroll
    for (int j = 0; j < 40; j++) {
        int idx = base + j;
        if (idx < N_NODES) { rowptr[idx] = run; run += cnt[idx]; }
    }
    if (t == 255) rowptr[N_NODES] = part[255];
}
__global__ void copy_cur(const int* __restrict__ rowptr, int* cur)
{
    int i = blockIdx.x * blockDim.x + threadIdx.x;
    if (i < N_NODES) cur[i] = rowptr[i];
}
__global__ void scatter_csr(const int* __restrict__ row, const int* __restrict__ col,
                            const float* __restrict__ val, int* cur,
                            int* __restrict__ oc, float* __restrict__ ov)
{
    int i = blockIdx.x * blockDim.x + threadIdx.x;
    if (i < E_EDGES) {
        int r = row[i];
        int p = atomicAdd(&cur[r], 1);
        oc[p] = col[i];
        ov[p] = val[i];
    }
}

// ================= fW softmax ==============================================
__global__ void fw_softmax(const float* __restrict__ fw_rna,
                           const float* __restrict__ fw_atac, float* out)
{
    int t = threadIdx.x;
    if (t >= 4) return;
    const float* src = (t < 2) ? (fw_rna + t * (K_HOPS + 1))
                               : (fw_atac + (t - 2) * (K_HOPS + 1));
    float m = -1e30f;
    for (int k = 0; k <= K_HOPS; k++) m = fmaxf(m, src[k]);
    float e[K_HOPS + 1];
    float s = 0.f;
    for (int k = 0; k <= K_HOPS; k++) { e[k] = expf(src[k] - m); s += e[k]; }
    float inv = 1.f / s;
    for (int k = 0; k <= K_HOPS; k++) out[t * (K_HOPS + 1) + k] = e[k] * inv;
}

// ================= propagation =============================================
// Fused hop (x4-unrolled, strictly sequential accumulation).
// w0p != null: acc = w0*x[row] + w*s; else acc += w*s. wx==0: skip xout store.
__global__ __launch_bounds__(256) void spmm_fused(
    const int* __restrict__ rowptr, const int* __restrict__ cols,
    const float* __restrict__ vals, const float* __restrict__ x,
    float* __restrict__ xout, float* __restrict__ acc,
    const float* __restrict__ wp, const float* __restrict__ w0p, int wx)
{
    int r = blockIdx.x * 8 + (threadIdx.x >> 5);
    if (r >= N_NODES) return;
    int lane = threadIdx.x & 31;
    float w = wp[0];
    int e0 = rowptr[r];
    int e1 = rowptr[r + 1];

    float4 s0 = make_float4(0.f, 0.f, 0.f, 0.f);
    float4 s1 = make_float4(0.f, 0.f, 0.f, 0.f);
    int e = e0;
    for (; e + 3 < e1; e += 4) {
        int c0 = cols[e];
        int c1 = cols[e + 1];
        int c2 = cols[e + 2];
        int c3 = cols[e + 3];
        float v0 = vals[e];
        float v1 = vals[e + 1];
        float v2 = vals[e + 2];
        float v3 = vals[e + 3];
        const float4* p0 = (const float4*)(x + (size_t)c0 * HID);
        const float4* p1 = (const float4*)(x + (size_t)c1 * HID);
        const float4* p2 = (const float4*)(x + (size_t)c2 * HID);
        const float4* p3 = (const float4*)(x + (size_t)c3 * HID);
        float4 a0 = p0[lane];
        float4 a1 = p0[lane + 32];
        float4 b0 = p1[lane];
        float4 b1 = p1[lane + 32];
        float4 d0 = p2[lane];
        float4 d1 = p2[lane + 32];
        float4 f0 = p3[lane];
        float4 f1 = p3[lane + 32];
        s0.x += v0 * a0.x; s0.y += v0 * a0.y; s0.z += v0 * a0.z; s0.w += v0 * a0.w;
        s1.x += v0 * a1.x; s1.y += v0 * a1.y; s1.z += v0 * a1.z; s1.w += v0 * a1.w;
        s0.x += v1 * b0.x; s0.y += v1 * b0.y; s0.z += v1 * b0.z; s0.w += v1 * b0.w;
        s1.x += v1 * b1.x; s1.y += v1 * b1.y; s1.z += v1 * b1.z; s1.w += v1 * b1.w;
        s0.x += v2 * d0.x; s0.y += v2 * d0.y; s0.z += v2 * d0.z; s0.w += v2 * d0.w;
        s1.x += v2 * d1.x; s1.y += v2 * d1.y; s1.z += v2 * d1.z; s1.w += v2 * d1.w;
        s0.x += v3 * f0.x; s0.y += v3 * f0.y; s0.z += v3 * f0.z; s0.w += v3 * f0.w;
        s1.x += v3 * f1.x; s1.y += v3 * f1.y; s1.z += v3 * f1.z; s1.w += v3 * f1.w;
    }
    for (; e < e1; e++) {
        int ca = cols[e];
        float va = vals[e];
        const float4* xa = (const float4*)(x + (size_t)ca * HID);
        float4 a0 = xa[lane];
        float4 a1 = xa[lane + 32];
        s0.x += va * a0.x; s0.y += va * a0.y; s0.z += va * a0.z; s0.w += va * a0.w;
        s1.x += va * a1.x; s1.y += va * a1.y; s1.z += va * a1.z; s1.w += va * a1.w;
    }

    if (wx) {
        float4* xo = (float4*)(xout + (size_t)r * HID);
        xo[lane] = s0;
        xo[lane + 32] = s1;
    }
    float4* ap = (float4*)(acc + (size_t)r * 512);
    if (w0p) {
        float w0 = w0p[0];
        const float4* xr = (const float4*)(x + (size_t)r * HID);
        float4 h0 = xr[lane];
        float4 h1 = xr[lane + 32];
        float4 q0, q1;
        q0.x = w0 * h0.x + w * s0.x; q0.y = w0 * h0.y + w * s0.y;
        q0.z = w0 * h0.z + w * s0.z; q0.w = w0 * h0.w + w * s0.w;
        q1.x = w0 * h1.x + w * s1.x; q1.y = w0 * h1.y + w * s1.y;
        q1.z = w0 * h1.z + w * s1.z; q1.w = w0 * h1.w + w * s1.w;
        ap[lane] = q0;
        ap[lane + 32] = q1;
    } else {
        float4 q0 = ap[lane];
        q0.x += w * s0.x; q0.y += w * s0.y; q0.z += w * s0.z; q0.w += w * s0.w;
        ap[lane] = q0;
        float4 q1 = ap[lane + 32];
        q1.x += w * s1.x; q1.y += w * s1.y; q1.z += w * s1.z; q1.w += w * s1.w;
        ap[lane + 32] = q1;
    }
}

// ================= attention fusion + z bf16-split conversion ==============
__global__ __launch_bounds__(256) void att_fuse_cv(
    const float* __restrict__ zr, const float* __restrict__ za,
    const float* __restrict__ Wa, const float* __restrict__ ba,
    float* __restrict__ z, float* __restrict__ wout,
    __nv_bfloat16* __restrict__ zcv)
{
    int r = blockIdx.x * 8 + (threadIdx.x >> 5);
    if (r >= N_NODES) return;
    int lane = threadIdx.x & 31;
    const float* zrr = zr + (long long)r * HID;
    const float* zar = za + (long long)r * HID;

    float p0 = 0.f;
    float p1 = 0.f;
    for (int c = lane; c < HID; c += 32) {
        float v = zrr[c];
        p0 += v * Wa[c * 2];
        p1 += v * Wa[c * 2 + 1];
        float u = zar[c];
        p0 += u * Wa[(HID + c) * 2];
        p1 += u * Wa[(HID + c) * 2 + 1];
    }
#pragma unroll
    for (int off = 16; off; off >>= 1) {
        p0 += __shfl_xor_sync(0xffffffffu, p0, off);
        p1 += __shfl_xor_sync(0xffffffffu, p1, off);
    }
    float l0 = p0 + ba[0];
    float l1 = p1 + ba[1];
    float m = fmaxf(l0, l1);
    float e0 = expf(l0 - m);
    float e1 = expf(l1 - m);
    float inv = 1.f / (e0 + e1);
    float w0 = e0 * inv;
    float w1 = e1 * inv;
    if (lane == 0) {
        wout[r * 2 + 0] = w0;
        wout[r * 2 + 1] = w1;
    }
    __nv_bfloat16* zc = zcv + (size_t)r * 768;
    for (int c = lane; c < HID; c += 32) {
        float zv = w0 * zrr[c] + w1 * zar[c];
        z[(long long)r * HID + c] = zv;
        __nv_bfloat16 hi = __float2bfloat16(zv);
        __nv_bfloat16 lo = __float2bfloat16(zv - __bfloat162float(hi));
        zc[c] = hi;
        zc[c + 256] = lo;
        zc[c + 512] = hi;
    }
}

// ================= host orchestration ======================================
static inline int cgrid(long long total, int tpb)
{
    long long b = (total + tpb - 1) / tpb;
    if (b > 65535) b = 65535;
    return (int)b;
}

// Streams/events created once on the FIRST call (before the harness's
// pre-capture baseline) and cached; the capture call allocates nothing.
static cudaStream_t g_s2 = 0;
static cudaStream_t g_s3 = 0;
static cudaEvent_t  g_ev[18];
static int          g_res_state = 0;

extern "C" void kernel_launch(void* const* d_in, const int* in_sizes, int n_in,
                              void* d_out, int out_size)
{
    const float* X_rna  = (const float*)d_in[0];
    const float* X_atac = (const float*)d_in[1];
    const int*   row1 = (const int*)d_in[2];
    const int*   col1 = (const int*)d_in[3];
    const float* val1 = (const float*)d_in[4];
    const int*   row2 = (const int*)d_in[5];
    const int*   col2 = (const int*)d_in[6];
    const float* val2 = (const float*)d_in[7];
    const float* Wi_rna  = (const float*)d_in[8];
    const float* bi_rna  = (const float*)d_in[9];
    const float* fW_rna  = (const float*)d_in[10];
    const float* Wo_rna  = (const float*)d_in[11];
    const float* bo_rna  = (const float*)d_in[12];
    const float* Wi_atac = (const float*)d_in[13];
    const float* bi_atac = (const float*)d_in[14];
    const float* fW_atac = (const float*)d_in[15];
    const float* Wo_atac = (const float*)d_in[16];
    const float* bo_atac = (const float*)d_in[17];
    const float* Wa = (const float*)d_in[18];
    const float* ba = (const float*)d_in[19];
    const float* Wd1_rna  = (const float*)d_in[20];
    const float* bd1_rna  = (const float*)d_in[21];
    const float* Wd2_rna  = (const float*)d_in[22];
    const float* bd2_rna  = (const float*)d_in[23];
    const float* Wd1_atac = (const float*)d_in[24];
    const float* bd1_atac = (const float*)d_in[25];
    const float* Wd2_atac = (const float*)d_in[26];
    const float* bd2_atac = (const float*)d_in[27];

    float* out = (float*)d_out;
    float* out_z     = out;
    float* out_zrna  = out + (size_t)N_NODES * HID;
    float* out_zatac = out + 2 * (size_t)N_NODES * HID;
    float* out_w     = out + 3 * (size_t)N_NODES * HID;
    float* out_rrec  = out_w + (size_t)N_NODES * 2;
    float* out_arec  = out_rrec + (size_t)N_NODES * D_RNA;

    float *pb0 = 0, *pb1 = 0, *pb2 = 0, *pb3 = 0, *pb4 = 0, *pb5 = 0, *pb6 = 0;
    float *pzr = 0, *pza = 0, *pfw = 0, *pvals = 0;
    int *prp = 0, *pcols = 0, *pcnt = 0, *pcur = 0;
    __nv_bfloat16 *pacr = 0, *paca = 0, *pawor = 0, *pawoa = 0;
    __nv_bfloat16 *paz = 0, *padr = 0, *pada = 0;
    __nv_bfloat16 *pwir0 = 0, *pwir1 = 0, *pwia0 = 0, *pwia1 = 0;
    __nv_bfloat16 *pwor = 0, *pwoa = 0, *pd1r = 0, *pd1a = 0, *pd2r = 0, *pd2a = 0;
    cudaGetSymbolAddress((void**)&pb0, g_b0);
    cudaGetSymbolAddress((void**)&pb1, g_b1);
    cudaGetSymbolAddress((void**)&pb2, g_b2);
    cudaGetSymbolAddress((void**)&pb3, g_b3);
    cudaGetSymbolAddress((void**)&pb4, g_b4);
    cudaGetSymbolAddress((void**)&pb5, g_b5);
    cudaGetSymbolAddress((void**)&pb6, g_b6);
    cudaGetSymbolAddress((void**)&pzr, g_zcr);
    cudaGetSymbolAddress((void**)&pza, g_zca);
    cudaGetSymbolAddress((void**)&pfw, g_fw);
    cudaGetSymbolAddress((void**)&prp, g_rowptr);
    cudaGetSymbolAddress((void**)&pcols, g_cols);
    cudaGetSymbolAddress((void**)&pvals, g_vals);
    cudaGetSymbolAddress((void**)&pcnt, g_cnt);
    cudaGetSymbolAddress((void**)&pcur, g_cur);
    cudaGetSymbolAddress((void**)&pacr, g_acr);
    cudaGetSymbolAddress((void**)&paca, g_aca);
    cudaGetSymbolAddress((void**)&pawor, g_awor);
    cudaGetSymbolAddress((void**)&pawoa, g_awoa);
    cudaGetSymbolAddress((void**)&paz, g_az);
    cudaGetSymbolAddress((void**)&padr, g_adr);
    cudaGetSymbolAddress((void**)&pada, g_ada);
    cudaGetSymbolAddress((void**)&pwir0, g_bwir0);
    cudaGetSymbolAddress((void**)&pwir1, g_bwir1);
    cudaGetSymbolAddress((void**)&pwia0, g_bwia0);
    cudaGetSymbolAddress((void**)&pwia1, g_bwia1);
    cudaGetSymbolAddress((void**)&pwor, g_bwor);
    cudaGetSymbolAddress((void**)&pwoa, g_bwoa);
    cudaGetSymbolAddress((void**)&pd1r, g_bd1r);
    cudaGetSymbolAddress((void**)&pd1a, g_bd1a);
    cudaGetSymbolAddress((void**)&pd2r, g_bd2r);
    cudaGetSymbolAddress((void**)&pd2a, g_bd2a);

    if (g_res_state == 0) {
        bool created = true;
        for (int i = 0; i < 18; i++) {
            if (created &&
                cudaEventCreateWithFlags(&g_ev[i], cudaEventDisableTiming) != cudaSuccess)
                created = false;
        }
        if (created &&
            cudaStreamCreateWithFlags(&g_s2, cudaStreamNonBlocking) != cudaSuccess)
            created = false;
        if (created &&
            cudaStreamCreateWithFlags(&g_s3, cudaStreamNonBlocking) != cudaSuccess)
            created = false;
        g_res_state = created ? 1 : -1;
    }
    const bool ok = (g_res_state == 1);
    cudaStream_t s2 = ok ? g_s2 : 0;
    cudaStream_t s3 = ok ? g_s3 : 0;
    cudaEvent_t eFork = g_ev[0], eAr = g_ev[1], eBw0 = g_ev[2], eCsr = g_ev[3];
    cudaEvent_t eGa1 = g_ev[4], eBwor = g_ev[5], eA0 = g_ev[6], eWcv = g_ev[7];
    cudaEvent_t eR0 = g_ev[8], eR1 = g_ev[9], eA1 = g_ev[10], eWoR = g_ev[11];
    cudaEvent_t eAtt = g_ev[12], eAda = g_ev[13], eDone2 = g_ev[14];
    cudaEvent_t eDone3 = g_ev[15];
#define REC(e, st) do { if (ok) cudaEventRecord(e, st); } while (0)
#define WAIT(st, e) do { if (ok) cudaStreamWaitEvent(st, e, 0); } while (0)

    const dim3 gH(2, 79);
    const int TPB = 256;
    const int* rp1 = prp;
    const int* rp2 = prp + (N_NODES + 1);
    const int* cs1 = pcols;
    const int* cs2 = pcols + E_EDGES;
    const float* vl1 = pvals;
    const float* vl2 = pvals + E_EDGES;

    // ---- s0 head: rna operand ----
    REC(eFork, 0);
    fw_softmax<<<1, 32>>>(fW_rna, fW_atac, pfw);
    conv_a<<<cgrid((long long)N_NODES * D_RNA / 2, TPB), TPB>>>(X_rna, pacr, N_NODES, D_RNA, 6016);
    pad_a<<<cgrid((long long)N_NODES * 16, TPB), TPB>>>(pacr, N_NODES, 6016, 6000);
    REC(eAr, 0);

    // ---- s2: CSR build ----
    WAIT(s2, eFork);
    for (int o = 0; o < 2; o++) {
        const int* rw = o ? row2 : row1;
        const int* cl = o ? col2 : col1;
        const float* vl = o ? val2 : val1;
        zero_cnt<<<40, 256, 0, s2>>>(pcnt + o * N_NODES);
        hist_rows<<<1250, 256, 0, s2>>>(rw, pcnt + o * N_NODES);
        exscan<<<1, 256, 0, s2>>>(pcnt + o * N_NODES, prp + o * (N_NODES + 1));
        copy_cur<<<40, 256, 0, s2>>>(prp + o * (N_NODES + 1), pcur + o * N_NODES);
        scatter_csr<<<1250, 256, 0, s2>>>(rw, cl, vl, pcur + o * N_NODES,
                                          pcols + o * E_EDGES, pvals + o * E_EDGES);
    }
    REC(eCsr, s2);

    // ---- s3: Wi_rna0 conv, atac Wi pipeline, Wo_rna conv, then A0 chain ---
    WAIT(s3, eFork);
    conv_b<<<cgrid((long long)D_RNA * HID / 2, TPB), TPB, 0, s3>>>(Wi_rna, pwir0, D_RNA, HID);
    pad_b<<<cgrid(16LL * HID, TPB), TPB, 0, s3>>>(pwir0 + (size_t)6000 * HID, 16 * HID);
    REC(eBw0, s3);
    conv_a<<<cgrid((long long)N_NODES * D_ATAC / 2, TPB), TPB, 0, s3>>>(
        X_atac, paca, N_NODES, D_ATAC, 15008);
    pad_a<<<cgrid((long long)N_NODES * 8, TPB), TPB, 0, s3>>>(paca, N_NODES, 15008, 15000);
    conv_b<<<cgrid((long long)D_ATAC * HID / 2, TPB), TPB, 0, s3>>>(Wi_atac, pwia0, D_ATAC, HID);
    pad_b<<<cgrid(8LL * HID, TPB), TPB, 0, s3>>>(pwia0 + (size_t)15000 * HID, 8 * HID);
    gemm_bf16<<<gH, 256, 0, s3>>>(paca, pwia0, bi_atac, pb3, N_NODES, HID, 15008, 0, 0);
    conv_b<<<cgrid((long long)D_ATAC * HID / 2, TPB), TPB, 0, s3>>>(
        Wi_atac + (size_t)D_ATAC * HID, pwia1, D_ATAC, HID);
    pad_b<<<cgrid(8LL * HID, TPB), TPB, 0, s3>>>(pwia1 + (size_t)15000 * HID, 8 * HID);
    gemm_bf16<<<gH, 256, 0, s3>>>(paca, pwia1, bi_atac + HID, pb4, N_NODES, HID, 15008, 0, 0);
    REC(eGa1, s3);
    conv_b<<<cgrid(512LL * HID / 2, TPB), TPB, 0, s3>>>(Wo_rna, pwor, 512, HID);
    REC(eBwor, s3);
    // A0 chain on s3: overlaps the remainder of the R-phase (3 chains live).
    WAIT(s3, eCsr);
    {
        const float* wrow = pfw + 2 * (K_HOPS + 1);
        float* bufs[2] = {pb3, pb6};
        for (int k = 1; k <= K_HOPS; k++)
            spmm_fused<<<1250, 256, 0, s3>>>(rp1, cs1, vl1,
                                             bufs[(k + 1) & 1], bufs[k & 1],
                                             pza, wrow + k,
                                             (k == 1) ? wrow : (const float*)0,
                                             (k < K_HOPS) ? 1 : 0);
    }
    REC(eA0, s3);
    // remaining weight conversions (consumed in the tail)
    conv_b<<<cgrid(512LL * HID / 2, TPB), TPB, 0, s3>>>(Wo_atac, pwoa, 512, HID);
    conv_b<<<cgrid((long long)HID * HID / 2, TPB), TPB, 0, s3>>>(Wd1_rna, pd1r, HID, HID);
    conv_b<<<cgrid((long long)HID * HID / 2, TPB), TPB, 0, s3>>>(Wd1_atac, pd1a, HID, HID);
    conv_b<<<cgrid((long long)HID * D_RNA / 2, TPB), TPB, 0, s3>>>(Wd2_rna, pd2r, HID, D_RNA);
    conv_b<<<cgrid((long long)HID * D_ATAC / 2, TPB), TPB, 0, s3>>>(Wd2_atac, pd2a, HID, D_ATAC);
    REC(eWcv, s3);

    // ---- s0: G_rna0 + R0 chain ----
    WAIT(0, eBw0);
    gemm_bf16<<<gH, 256>>>(pacr, pwir0, bi_rna, pb0, N_NODES, HID, 6016, 0, 0);
    WAIT(0, eCsr);
    {
        const float* wrow = pfw;
        float* bufs[2] = {pb0, pb1};
        for (int k = 1; k <= K_HOPS; k++)
            spmm_fused<<<1250, 256>>>(rp1, cs1, vl1,
                                      bufs[(k + 1) & 1], bufs[k & 1], pzr, wrow + k,
                                      (k == 1) ? wrow : (const float*)0,
                                      (k < K_HOPS) ? 1 : 0);
    }
    REC(eR0, 0);

    // ---- s2: G_rna1 + R1 chain, then A1 chain ----
    WAIT(s2, eAr);
    conv_b<<<cgrid((long long)D_RNA * HID / 2, TPB), TPB, 0, s2>>>(
        Wi_rna + (size_t)D_RNA * HID, pwir1, D_RNA, HID);
    pad_b<<<cgrid(16LL * HID, TPB), TPB, 0, s2>>>(pwir1 + (size_t)6000 * HID, 16 * HID);
    gemm_bf16<<<gH, 256, 0, s2>>>(pacr, pwir1, bi_rna + HID, pb2, N_NODES, HID, 6016, 0, 0);
    {
        const float* wrow = pfw + (K_HOPS + 1);
        float* bufs[2] = {pb2, pb5};
        for (int k = 1; k <= K_HOPS; k++)
            spmm_fused<<<1250, 256, 0, s2>>>(rp2, cs2, vl2,
                                             bufs[(k + 1) & 1], bufs[k & 1],
                                             pzr + HID, wrow + k,
                                             (k == 1) ? wrow : (const float*)0,
                                             (k < K_HOPS) ? 1 : 0);
    }
    REC(eR1, s2);
    WAIT(s2, eGa1);
    {
        const float* wrow = pfw + 3 * (K_HOPS + 1);
        float* bufs[2] = {pb4, pb2};
        for (int k = 1; k <= K_HOPS; k++)
            spmm_fused<<<1250, 256, 0, s2>>>(rp2, cs2, vl2,
                                             bufs[(k + 1) & 1], bufs[k & 1],
                                             pza + HID, wrow + k,
                                             (k == 1) ? wrow : (const float*)0,
                                             (k < K_HOPS) ? 1 : 0);
    }
    REC(eA1, s2);

    // ---- s0: Wo_rna (after R0 serial + R1), then tail ----
    WAIT(0, eR1);
    WAIT(0, eBwor);
    conv_a<<<cgrid((long long)N_NODES * 512 / 2, TPB), TPB>>>(pzr, pawor, N_NODES, 512, 1536);
    gemm_bf16<<<gH, 256>>>(pawor, pwor, bo_rna, out_zrna, N_NODES, HID, 1536, 0, 0);
    REC(eWoR, 0);

    // ---- s0: Wo_atac + attention ----
    WAIT(0, eA0);
    WAIT(0, eA1);
    WAIT(0, eWcv);
    conv_a<<<cgrid((long long)N_NODES * 512 / 2, TPB), TPB>>>(pza, pawoa, N_NODES, 512, 1536);
    gemm_bf16<<<gH, 256>>>(pawoa, pwoa, bo_atac, out_zatac, N_NODES, HID, 1536, 0, 0);
    att_fuse_cv<<<1250, 256>>>(out_zrna, out_zatac, Wa, ba, out_z, out_w, paz);
    REC(eAtt, 0);

    // ---- s2: rna decoder ----
    WAIT(s2, eAtt);
    WAIT(s2, eWcv);
    gemm_bf16<<<gH, 256, 0, s2>>>(paz, pd1r, bd1_rna, pb2, N_NODES, HID, 768, 1, 0);
    conv_a<<<cgrid((long long)N_NODES * HID / 2, TPB), TPB, 0, s2>>>(pb2, padr, N_NODES, HID, 768);
    gemm_bf16<<<dim3(16, 79), 256, 0, s2>>>(padr, pd2r, bd2_rna, out_rrec,
                                            N_NODES, D_RNA, 768, 0, 0);

    // ---- s0: atac decoder layer 1 + first slice of d2 ----
    gemm_bf16<<<gH, 256>>>(paz, pd1a, bd1_atac, pb3, N_NODES, HID, 768, 1, 0);
    conv_a<<<cgrid((long long)N_NODES * HID / 2, TPB), TPB>>>(pb3, pada, N_NODES, HID, 768);
    REC(eAda, 0);
    gemm_bf16<<<dim3(14, 79), 256>>>(pada, pd2a, bd2_atac, out_arec,
                                     N_NODES, D_ATAC, 768, 0, 0);

    // ---- s2: second slice of atac d2 ----
    WAIT(s2, eAda);
    gemm_bf16<<<dim3(13, 79), 256, 0, s2>>>(pada, pd2a, bd2_atac, out_arec,
                                            N_NODES, D_ATAC, 768, 0, 14);
    REC(eDone2, s2);

    // ---- s3: third slice of atac d2 ----
    WAIT(s3, eAda);
    gemm_bf16<<<dim3(13, 79), 256, 0, s3>>>(pada, pd2a, bd2_atac, out_arec,
                                            N_NODES, D_ATAC, 768, 0, 27);
    REC(eDone3, s3);

    WAIT(0, eDone2);
    WAIT(0, eDone3);
#undef REC
#undef WAIT
}

// round 16
// speedup vs baseline: 1.0410x; 1.0410x over previous
#include <cuda_runtime.h>
#include <cuda_bf16.h>
#include <cstdint>

#define N_NODES 10000
#define E_EDGES 320000
#define HID 256
#define K_HOPS 10
#define D_RNA 2000
#define D_ATAC 5000

// ---------------- scratch (static device allocations; no cudaMalloc) -------
__device__ float g_b0[N_NODES * HID];
__device__ float g_b1[N_NODES * HID];
__device__ float g_b2[N_NODES * HID];
__device__ float g_b3[N_NODES * HID];
__device__ float g_b4[N_NODES * HID];
__device__ float g_b5[N_NODES * HID];
__device__ float g_zcr[N_NODES * 2 * HID];
__device__ float g_zca[N_NODES * 2 * HID];
__device__ float g_fw[4 * (K_HOPS + 1)];
__device__ int   g_rowptr[2 * (N_NODES + 1)];
__device__ int   g_cols[2 * E_EDGES];
__device__ float g_vals[2 * E_EDGES];
__device__ int   g_cnt[2 * N_NODES];
__device__ int   g_cur[2 * N_NODES];
// split-bf16 operand buffers
__device__ __nv_bfloat16 g_acr[(size_t)N_NODES * 6016];
__device__ __nv_bfloat16 g_aca[(size_t)N_NODES * 15008];
__device__ __nv_bfloat16 g_awor[(size_t)N_NODES * 1536];
__device__ __nv_bfloat16 g_awoa[(size_t)N_NODES * 1536];
__device__ __nv_bfloat16 g_az[(size_t)N_NODES * 768];
__device__ __nv_bfloat16 g_adr[(size_t)N_NODES * 768];
__device__ __nv_bfloat16 g_ada[(size_t)N_NODES * 768];
__device__ __nv_bfloat16 g_bwir0[6016 * 256];
__device__ __nv_bfloat16 g_bwir1[6016 * 256];
__device__ __nv_bfloat16 g_bwia0[15008 * 256];
__device__ __nv_bfloat16 g_bwia1[15008 * 256];
__device__ __nv_bfloat16 g_bwor[1536 * 256];
__device__ __nv_bfloat16 g_bwoa[1536 * 256];
__device__ __nv_bfloat16 g_bd1r[768 * 256];
__device__ __nv_bfloat16 g_bd1a[768 * 256];
__device__ __nv_bfloat16 g_bd2r[768 * 2000];
__device__ __nv_bfloat16 g_bd2a[768 * 5000];

// ================= split-bf16 conversion kernels ===========================
__global__ void conv_a(const float* __restrict__ A, __nv_bfloat16* __restrict__ out,
                       int M, int K, int Kcp)
{
    int kh = K >> 1;
    int total = M * kh;
    for (int i = blockIdx.x * blockDim.x + threadIdx.x; i < total;
         i += gridDim.x * blockDim.x) {
        int m = i / kh;
        int k = (i - m * kh) * 2;
        float2 x = *(const float2*)(A + (size_t)m * K + k);
        __nv_bfloat16 h0 = __float2bfloat16(x.x);
        __nv_bfloat16 h1 = __float2bfloat16(x.y);
        __nv_bfloat16 l0 = __float2bfloat16(x.x - __bfloat162float(h0));
        __nv_bfloat16 l1 = __float2bfloat16(x.y - __bfloat162float(h1));
        __nv_bfloat162 hp; hp.x = h0; hp.y = h1;
        __nv_bfloat162 lp; lp.x = l0; lp.y = l1;
        size_t base = (size_t)m * Kcp + k;
        *(__nv_bfloat162*)(out + base) = hp;
        *(__nv_bfloat162*)(out + base + K) = lp;
        *(__nv_bfloat162*)(out + base + 2 * K) = hp;
    }
}

__global__ void pad_a(__nv_bfloat16* out, int M, int Kcp, int start)
{
    int w = Kcp - start;
    int total = M * w;
    for (int i = blockIdx.x * blockDim.x + threadIdx.x; i < total;
         i += gridDim.x * blockDim.x) {
        int m = i / w;
        int j = i - m * w;
        out[(size_t)m * Kcp + start + j] = __float2bfloat16(0.f);
    }
}

__global__ void conv_b(const float* __restrict__ B, __nv_bfloat16* __restrict__ out,
                       int K, int N)
{
    int nh = N >> 1;
    int total = K * nh;
    for (int i = blockIdx.x * blockDim.x + threadIdx.x; i < total;
         i += gridDim.x * blockDim.x) {
        int k = i / nh;
        int n = (i - k * nh) * 2;
        float2 x = *(const float2*)(B + (size_t)k * N + n);
        __nv_bfloat16 h0 = __float2bfloat16(x.x);
        __nv_bfloat16 h1 = __float2bfloat16(x.y);
        __nv_bfloat16 l0 = __float2bfloat16(x.x - __bfloat162float(h0));
        __nv_bfloat16 l1 = __float2bfloat16(x.y - __bfloat162float(h1));
        __nv_bfloat162 hp; hp.x = h0; hp.y = h1;
        __nv_bfloat162 lp; lp.x = l0; lp.y = l1;
        *(__nv_bfloat162*)(out + (size_t)k * N + n) = hp;
        *(__nv_bfloat162*)(out + (size_t)(K + k) * N + n) = hp;
        *(__nv_bfloat162*)(out + (size_t)(2 * K + k) * N + n) = lp;
    }
}

__global__ void pad_b(__nv_bfloat16* out, int count)
{
    for (int i = blockIdx.x * blockDim.x + threadIdx.x; i < count;
         i += gridDim.x * blockDim.x)
        out[i] = __float2bfloat16(0.f);
}

// ================= bf16 tensor-core GEMM ===================================
__device__ __forceinline__ void cpa16(void* sm, const void* gm, bool p)
{
    unsigned int s = (unsigned int)__cvta_generic_to_shared(sm);
    int sz = p ? 16 : 0;
    asm volatile("cp.async.cg.shared.global [%0], [%1], 16, %2;"
                 :: "r"(s), "l"(gm), "r"(sz) : "memory");
}
__device__ __forceinline__ void ldsm4(unsigned int* d, const void* p)
{
    unsigned int s = (unsigned int)__cvta_generic_to_shared(p);
    asm volatile("ldmatrix.sync.aligned.m8n8.x4.shared.b16 {%0,%1,%2,%3}, [%4];"
                 : "=r"(d[0]), "=r"(d[1]), "=r"(d[2]), "=r"(d[3]) : "r"(s));
}
__device__ __forceinline__ void ldsm4t(unsigned int* d, const void* p)
{
    unsigned int s = (unsigned int)__cvta_generic_to_shared(p);
    asm volatile("ldmatrix.sync.aligned.m8n8.x4.trans.shared.b16 {%0,%1,%2,%3}, [%4];"
                 : "=r"(d[0]), "=r"(d[1]), "=r"(d[2]), "=r"(d[3]) : "r"(s));
}
__device__ __forceinline__ void mma16816(float* c, const unsigned int* a,
                                         unsigned int b0, unsigned int b1)
{
    asm volatile("mma.sync.aligned.m16n8k16.row.col.f32.bf16.bf16.f32 "
                 "{%0,%1,%2,%3}, {%4,%5,%6,%7}, {%8,%9}, {%0,%1,%2,%3};"
                 : "+f"(c[0]), "+f"(c[1]), "+f"(c[2]), "+f"(c[3])
                 : "r"(a[0]), "r"(a[1]), "r"(a[2]), "r"(a[3]), "r"(b0), "r"(b1));
}

__global__ __launch_bounds__(256, 2) void gemm_bf16(
    const __nv_bfloat16* __restrict__ A, const __nv_bfloat16* __restrict__ B,
    const float* __restrict__ bias, float* __restrict__ C,
    int M, int N, int Kc, int relu, int colBase)
{
    __shared__ __nv_bfloat16 As[2][128][40];
    __shared__ __nv_bfloat16 Bs[2][32][136];

    const int tid = threadIdx.x;
    const int lane = tid & 31;
    const int warp = tid >> 5;
    const int wm = warp >> 2;
    const int wn = warp & 3;
    const int row0 = blockIdx.y * 128;
    const int col0 = (blockIdx.x + colBase) * 128;

    const int ar = tid >> 1;
    const int ac = (tid & 1) << 4;
    const int arow = row0 + ar;
    const bool apred = arow < M;
    const __nv_bfloat16* Abase = A + (size_t)(apred ? arow : 0) * Kc + ac;

    const int br = tid >> 3;
    const int bc = (tid & 7) << 4;
    const int bcol = col0 + bc;
    const bool bp0 = bcol < N;
    const bool bp1 = (bcol + 8) < N;
    const int bc0 = bp0 ? bcol : 0;
    const int bc1 = bp1 ? (bcol + 8) : 0;

    float acc[4][4][4];
#pragma unroll
    for (int i = 0; i < 4; i++) {
#pragma unroll
        for (int j = 0; j < 4; j++) {
#pragma unroll
            for (int q = 0; q < 4; q++) acc[i][j][q] = 0.f;
        }
    }

    const int iters = Kc >> 5;

    cpa16(&As[0][ar][ac], Abase, apred);
    cpa16(&As[0][ar][ac + 8], Abase + 8, apred);
    {
        const __nv_bfloat16* Bb = B + (size_t)br * N;
        cpa16(&Bs[0][br][bc], Bb + bc0, bp0);
        cpa16(&Bs[0][br][bc + 8], Bb + bc1, bp1);
    }
    asm volatile("cp.async.commit_group;" ::: "memory");

    int s = 0;
    for (int it = 0; it < iters; it++) {
        if (it + 1 < iters) {
            const int kk = (it + 1) << 5;
            cpa16(&As[s ^ 1][ar][ac], Abase + kk, apred);
            cpa16(&As[s ^ 1][ar][ac + 8], Abase + kk + 8, apred);
            const __nv_bfloat16* Bb = B + (size_t)(kk + br) * N;
            cpa16(&Bs[s ^ 1][br][bc], Bb + bc0, bp0);
            cpa16(&Bs[s ^ 1][br][bc + 8], Bb + bc1, bp1);
            asm volatile("cp.async.commit_group;" ::: "memory");
            asm volatile("cp.async.wait_group 1;" ::: "memory");
        } else {
            asm volatile("cp.async.wait_group 0;" ::: "memory");
        }
        __syncthreads();

#pragma unroll
        for (int k16 = 0; k16 < 2; k16++) {
            unsigned int af[4][4];
#pragma unroll
            for (int mi = 0; mi < 4; mi++) {
                ldsm4(af[mi], &As[s][wm * 64 + mi * 16 + (lane & 15)]
                                    [k16 * 16 + ((lane >> 4) << 3)]);
            }
            unsigned int bfr[2][4];
#pragma unroll
            for (int g = 0; g < 2; g++) {
                ldsm4t(bfr[g], &Bs[s][k16 * 16 + (lane & 15)]
                                     [wn * 32 + g * 16 + ((lane >> 4) << 3)]);
            }
#pragma unroll
            for (int mi = 0; mi < 4; mi++) {
#pragma unroll
                for (int ni = 0; ni < 4; ni++) {
                    mma16816(acc[mi][ni], af[mi],
                             bfr[ni >> 1][(ni & 1) * 2],
                             bfr[ni >> 1][(ni & 1) * 2 + 1]);
                }
            }
        }
        __syncthreads();
        s ^= 1;
    }

#pragma unroll
    for (int mi = 0; mi < 4; mi++) {
        int r = row0 + wm * 64 + mi * 16 + (lane >> 2);
#pragma unroll
        for (int ni = 0; ni < 4; ni++) {
            int c = col0 + wn * 32 + ni * 8 + ((lane & 3) << 1);
            if (c < N) {
                float b0 = bias[c];
                float b1 = bias[c + 1];
                if (r < M) {
                    float o0 = acc[mi][ni][0] + b0;
                    float o1 = acc[mi][ni][1] + b1;
                    if (relu) { o0 = fmaxf(o0, 0.f); o1 = fmaxf(o1, 0.f); }
                    *(float2*)(C + (size_t)r * N + c) = make_float2(o0, o1);
                }
                if (r + 8 < M) {
                    float o2 = acc[mi][ni][2] + b0;
                    float o3 = acc[mi][ni][3] + b1;
                    if (relu) { o2 = fmaxf(o2, 0.f); o3 = fmaxf(o3, 0.f); }
                    *(float2*)(C + (size_t)(r + 8) * N + c) = make_float2(o2, o3);
                }
            }
        }
    }
}

// ================= CSR construction ========================================
__global__ void zero_cnt(int* cnt)
{
    int i = blockIdx.x * blockDim.x + threadIdx.x;
    if (i < N_NODES) cnt[i] = 0;
}
__global__ void hist_rows(const int* __restrict__ row, int* cnt)
{
    int i = blockIdx.x * blockDim.x + threadIdx.x;
    if (i < E_EDGES) atomicAdd(&cnt[row[i]], 1);
}
__global__ void exscan(const int* __restrict__ cnt, int* rowptr)
{
    __shared__ int part[256];
    int t = threadIdx.x;
    int base = t * 40;
    int s = 0;
#pragma unroll
    for (int j = 0; j < 40; j++) {
        int idx = base + j;
        if (idx < N_NODES) s += cnt[idx];
    }
    part[t] = s;
    __syncthreads();
    for (int off = 1; off < 256; off <<= 1) {
        int v = (t >= off) ? part[t - off] : 0;
        __syncthreads();
        part[t] += v;
        __syncthreads();
    }
    int run = (t > 0) ? part[t - 1] : 0;
#pragma unroll
    for (int j = 0; j < 40; j++) {
        int idx = base + j;
        if (idx < N_NODES) { rowptr[idx] = run; run += cnt[idx]; }
    }
    if (t == 255) rowptr[N_NODES] = part[255];
}
__global__ void copy_cur(const int* __restrict__ rowptr, int* cur)
{
    int i = blockIdx.x * blockDim.x + threadIdx.x;
    if (i < N_NODES) cur[i] = rowptr[i];
}
__global__ void scatter_csr(const int* __restrict__ row, const int* __restrict__ col,
                            const float* __restrict__ val, int* cur,
                            int* __restrict__ oc, float* __restrict__ ov)
{
    int i = blockIdx.x * blockDim.x + threadIdx.x;
    if (i < E_EDGES) {
        int r = row[i];
        int p = atomicAdd(&cur[r], 1);
        oc[p] = col[i];
        ov[p] = val[i];
    }
}

// ================= fW softmax ==============================================
__global__ void fw_softmax(const float* __restrict__ fw_rna,
                           const float* __restrict__ fw_atac, float* out)
{
    int t = threadIdx.x;
    if (t >= 4) return;
    const float* src = (t < 2) ? (fw_rna + t * (K_HOPS + 1))
                               : (fw_atac + (t - 2) * (K_HOPS + 1));
    float m = -1e30f;
    for (int k = 0; k <= K_HOPS; k++) m = fmaxf(m, src[k]);
    float e[K_HOPS + 1];
    float s = 0.f;
    for (int k = 0; k <= K_HOPS; k++) { e[k] = expf(src[k] - m); s += e[k]; }
    float inv = 1.f / s;
    for (int k = 0; k <= K_HOPS; k++) out[t * (K_HOPS + 1) + k] = e[k] * inv;
}

// ================= propagation =============================================
// Fused hop, edge loop unrolled x4 for deeper MLP. Accumulation remains
// STRICTLY sequential in edge order (bit-identical result to the x2 version).
// If w0p != null (first hop): acc = w0*x[row] + w*s; else acc += w*s.
// If wx==0 the xout store is skipped (final hop, dead value).
__global__ __launch_bounds__(256) void spmm_fused(
    const int* __restrict__ rowptr, const int* __restrict__ cols,
    const float* __restrict__ vals, const float* __restrict__ x,
    float* __restrict__ xout, float* __restrict__ acc,
    const float* __restrict__ wp, const float* __restrict__ w0p, int wx)
{
    int r = blockIdx.x * 8 + (threadIdx.x >> 5);
    if (r >= N_NODES) return;
    int lane = threadIdx.x & 31;
    float w = wp[0];
    int e0 = rowptr[r];
    int e1 = rowptr[r + 1];

    float4 s0 = make_float4(0.f, 0.f, 0.f, 0.f);
    float4 s1 = make_float4(0.f, 0.f, 0.f, 0.f);
    int e = e0;
    for (; e + 3 < e1; e += 4) {
        int c0 = cols[e];
        int c1 = cols[e + 1];
        int c2 = cols[e + 2];
        int c3 = cols[e + 3];
        float v0 = vals[e];
        float v1 = vals[e + 1];
        float v2 = vals[e + 2];
        float v3 = vals[e + 3];
        const float4* p0 = (const float4*)(x + (size_t)c0 * HID);
        const float4* p1 = (const float4*)(x + (size_t)c1 * HID);
        const float4* p2 = (const float4*)(x + (size_t)c2 * HID);
        const float4* p3 = (const float4*)(x + (size_t)c3 * HID);
        float4 a0 = p0[lane];
        float4 a1 = p0[lane + 32];
        float4 b0 = p1[lane];
        float4 b1 = p1[lane + 32];
        float4 d0 = p2[lane];
        float4 d1 = p2[lane + 32];
        float4 f0 = p3[lane];
        float4 f1 = p3[lane + 32];
        s0.x += v0 * a0.x; s0.y += v0 * a0.y; s0.z += v0 * a0.z; s0.w += v0 * a0.w;
        s1.x += v0 * a1.x; s1.y += v0 * a1.y; s1.z += v0 * a1.z; s1.w += v0 * a1.w;
        s0.x += v1 * b0.x; s0.y += v1 * b0.y; s0.z += v1 * b0.z; s0.w += v1 * b0.w;
        s1.x += v1 * b1.x; s1.y += v1 * b1.y; s1.z += v1 * b1.z; s1.w += v1 * b1.w;
        s0.x += v2 * d0.x; s0.y += v2 * d0.y; s0.z += v2 * d0.z; s0.w += v2 * d0.w;
        s1.x += v2 * d1.x; s1.y += v2 * d1.y; s1.z += v2 * d1.z; s1.w += v2 * d1.w;
        s0.x += v3 * f0.x; s0.y += v3 * f0.y; s0.z += v3 * f0.z; s0.w += v3 * f0.w;
        s1.x += v3 * f1.x; s1.y += v3 * f1.y; s1.z += v3 * f1.z; s1.w += v3 * f1.w;
    }
    for (; e < e1; e++) {
        int ca = cols[e];
        float va = vals[e];
        const float4* xa = (const float4*)(x + (size_t)ca * HID);
        float4 a0 = xa[lane];
        float4 a1 = xa[lane + 32];
        s0.x += va * a0.x; s0.y += va * a0.y; s0.z += va * a0.z; s0.w += va * a0.w;
        s1.x += va * a1.x; s1.y += va * a1.y; s1.z += va * a1.z; s1.w += va * a1.w;
    }

    if (wx) {
        float4* xo = (float4*)(xout + (size_t)r * HID);
        xo[lane] = s0;
        xo[lane + 32] = s1;
    }
    float4* ap = (float4*)(acc + (size_t)r * 512);
    if (w0p) {
        float w0 = w0p[0];
        const float4* xr = (const float4*)(x + (size_t)r * HID);
        float4 h0 = xr[lane];
        float4 h1 = xr[lane + 32];
        float4 q0, q1;
        q0.x = w0 * h0.x + w * s0.x; q0.y = w0 * h0.y + w * s0.y;
        q0.z = w0 * h0.z + w * s0.z; q0.w = w0 * h0.w + w * s0.w;
        q1.x = w0 * h1.x + w * s1.x; q1.y = w0 * h1.y + w * s1.y;
        q1.z = w0 * h1.z + w * s1.z; q1.w = w0 * h1.w + w * s1.w;
        ap[lane] = q0;
        ap[lane + 32] = q1;
    } else {
        float4 q0 = ap[lane];
        q0.x += w * s0.x; q0.y += w * s0.y; q0.z += w * s0.z; q0.w += w * s0.w;
        ap[lane] = q0;
        float4 q1 = ap[lane + 32];
        q1.x += w * s1.x; q1.y += w * s1.y; q1.z += w * s1.z; q1.w += w * s1.w;
        ap[lane + 32] = q1;
    }
}

// ================= attention fusion + z bf16-split conversion ==============
__global__ __launch_bounds__(256) void att_fuse_cv(
    const float* __restrict__ zr, const float* __restrict__ za,
    const float* __restrict__ Wa, const float* __restrict__ ba,
    float* __restrict__ z, float* __restrict__ wout,
    __nv_bfloat16* __restrict__ zcv)
{
    int r = blockIdx.x * 8 + (threadIdx.x >> 5);
    if (r >= N_NODES) return;
    int lane = threadIdx.x & 31;
    const float* zrr = zr + (long long)r * HID;
    const float* zar = za + (long long)r * HID;

    float p0 = 0.f;
    float p1 = 0.f;
    for (int c = lane; c < HID; c += 32) {
        float v = zrr[c];
        p0 += v * Wa[c * 2];
        p1 += v * Wa[c * 2 + 1];
        float u = zar[c];
        p0 += u * Wa[(HID + c) * 2];
        p1 += u * Wa[(HID + c) * 2 + 1];
    }
#pragma unroll
    for (int off = 16; off; off >>= 1) {
        p0 += __shfl_xor_sync(0xffffffffu, p0, off);
        p1 += __shfl_xor_sync(0xffffffffu, p1, off);
    }
    float l0 = p0 + ba[0];
    float l1 = p1 + ba[1];
    float m = fmaxf(l0, l1);
    float e0 = expf(l0 - m);
    float e1 = expf(l1 - m);
    float inv = 1.f / (e0 + e1);
    float w0 = e0 * inv;
    float w1 = e1 * inv;
    if (lane == 0) {
        wout[r * 2 + 0] = w0;
        wout[r * 2 + 1] = w1;
    }
    __nv_bfloat16* zc = zcv + (size_t)r * 768;
    for (int c = lane; c < HID; c += 32) {
        float zv = w0 * zrr[c] + w1 * zar[c];
        z[(long long)r * HID + c] = zv;
        __nv_bfloat16 hi = __float2bfloat16(zv);
        __nv_bfloat16 lo = __float2bfloat16(zv - __bfloat162float(hi));
        zc[c] = hi;
        zc[c + 256] = lo;
        zc[c + 512] = hi;
    }
}

// ================= host orchestration ======================================
static inline int cgrid(long long total, int tpb)
{
    long long b = (total + tpb - 1) / tpb;
    if (b > 65535) b = 65535;
    return (int)b;
}

// Streams/events created once on the FIRST call (before the harness's
// pre-capture baseline) and cached; the capture call allocates nothing.
static cudaStream_t g_s2 = 0;
static cudaStream_t g_s3 = 0;
static cudaEvent_t  g_ev[17];
static int          g_res_state = 0;

extern "C" void kernel_launch(void* const* d_in, const int* in_sizes, int n_in,
                              void* d_out, int out_size)
{
    const float* X_rna  = (const float*)d_in[0];
    const float* X_atac = (const float*)d_in[1];
    const int*   row1 = (const int*)d_in[2];
    const int*   col1 = (const int*)d_in[3];
    const float* val1 = (const float*)d_in[4];
    const int*   row2 = (const int*)d_in[5];
    const int*   col2 = (const int*)d_in[6];
    const float* val2 = (const float*)d_in[7];
    const float* Wi_rna  = (const float*)d_in[8];
    const float* bi_rna  = (const float*)d_in[9];
    const float* fW_rna  = (const float*)d_in[10];
    const float* Wo_rna  = (const float*)d_in[11];
    const float* bo_rna  = (const float*)d_in[12];
    const float* Wi_atac = (const float*)d_in[13];
    const float* bi_atac = (const float*)d_in[14];
    const float* fW_atac = (const float*)d_in[15];
    const float* Wo_atac = (const float*)d_in[16];
    const float* bo_atac = (const float*)d_in[17];
    const float* Wa = (const float*)d_in[18];
    const float* ba = (const float*)d_in[19];
    const float* Wd1_rna  = (const float*)d_in[20];
    const float* bd1_rna  = (const float*)d_in[21];
    const float* Wd2_rna  = (const float*)d_in[22];
    const float* bd2_rna  = (const float*)d_in[23];
    const float* Wd1_atac = (const float*)d_in[24];
    const float* bd1_atac = (const float*)d_in[25];
    const float* Wd2_atac = (const float*)d_in[26];
    const float* bd2_atac = (const float*)d_in[27];

    float* out = (float*)d_out;
    float* out_z     = out;
    float* out_zrna  = out + (size_t)N_NODES * HID;
    float* out_zatac = out + 2 * (size_t)N_NODES * HID;
    float* out_w     = out + 3 * (size_t)N_NODES * HID;
    float* out_rrec  = out_w + (size_t)N_NODES * 2;
    float* out_arec  = out_rrec + (size_t)N_NODES * D_RNA;

    float *pb0 = 0, *pb1 = 0, *pb2 = 0, *pb3 = 0, *pb4 = 0, *pb5 = 0;
    float *pzr = 0, *pza = 0, *pfw = 0, *pvals = 0;
    int *prp = 0, *pcols = 0, *pcnt = 0, *pcur = 0;
    __nv_bfloat16 *pacr = 0, *paca = 0, *pawor = 0, *pawoa = 0;
    __nv_bfloat16 *paz = 0, *padr = 0, *pada = 0;
    __nv_bfloat16 *pwir0 = 0, *pwir1 = 0, *pwia0 = 0, *pwia1 = 0;
    __nv_bfloat16 *pwor = 0, *pwoa = 0, *pd1r = 0, *pd1a = 0, *pd2r = 0, *pd2a = 0;
    cudaGetSymbolAddress((void**)&pb0, g_b0);
    cudaGetSymbolAddress((void**)&pb1, g_b1);
    cudaGetSymbolAddress((void**)&pb2, g_b2);
    cudaGetSymbolAddress((void**)&pb3, g_b3);
    cudaGetSymbolAddress((void**)&pb4, g_b4);
    cudaGetSymbolAddress((void**)&pb5, g_b5);
    cudaGetSymbolAddress((void**)&pzr, g_zcr);
    cudaGetSymbolAddress((void**)&pza, g_zca);
    cudaGetSymbolAddress((void**)&pfw, g_fw);
    cudaGetSymbolAddress((void**)&prp, g_rowptr);
    cudaGetSymbolAddress((void**)&pcols, g_cols);
    cudaGetSymbolAddress((void**)&pvals, g_vals);
    cudaGetSymbolAddress((void**)&pcnt, g_cnt);
    cudaGetSymbolAddress((void**)&pcur, g_cur);
    cudaGetSymbolAddress((void**)&pacr, g_acr);
    cudaGetSymbolAddress((void**)&paca, g_aca);
    cudaGetSymbolAddress((void**)&pawor, g_awor);
    cudaGetSymbolAddress((void**)&pawoa, g_awoa);
    cudaGetSymbolAddress((void**)&paz, g_az);
    cudaGetSymbolAddress((void**)&padr, g_adr);
    cudaGetSymbolAddress((void**)&pada, g_ada);
    cudaGetSymbolAddress((void**)&pwir0, g_bwir0);
    cudaGetSymbolAddress((void**)&pwir1, g_bwir1);
    cudaGetSymbolAddress((void**)&pwia0, g_bwia0);
    cudaGetSymbolAddress((void**)&pwia1, g_bwia1);
    cudaGetSymbolAddress((void**)&pwor, g_bwor);
    cudaGetSymbolAddress((void**)&pwoa, g_bwoa);
    cudaGetSymbolAddress((void**)&pd1r, g_bd1r);
    cudaGetSymbolAddress((void**)&pd1a, g_bd1a);
    cudaGetSymbolAddress((void**)&pd2r, g_bd2r);
    cudaGetSymbolAddress((void**)&pd2a, g_bd2a);

    if (g_res_state == 0) {
        bool created = true;
        for (int i = 0; i < 17; i++) {
            if (created &&
                cudaEventCreateWithFlags(&g_ev[i], cudaEventDisableTiming) != cudaSuccess)
                created = false;
        }
        if (created &&
            cudaStreamCreateWithFlags(&g_s2, cudaStreamNonBlocking) != cudaSuccess)
            created = false;
        if (created &&
            cudaStreamCreateWithFlags(&g_s3, cudaStreamNonBlocking) != cudaSuccess)
            created = false;
        g_res_state = created ? 1 : -1;
    }
    const bool ok = (g_res_state == 1);
    cudaStream_t s2 = ok ? g_s2 : 0;
    cudaStream_t s3 = ok ? g_s3 : 0;
    cudaEvent_t eFork = g_ev[0], eAr = g_ev[1], eBw0 = g_ev[2], eCsr = g_ev[3];
    cudaEvent_t eGa0 = g_ev[4], eGa1 = g_ev[5], eWcv = g_ev[6], eR0 = g_ev[7];
    cudaEvent_t eR1 = g_ev[8], eA1 = g_ev[9], eWoR = g_ev[10], eWoaC = g_ev[11];
    cudaEvent_t eWoa1 = g_ev[12], eAtt = g_ev[13], eAda = g_ev[14];
    cudaEvent_t eDone2 = g_ev[15], eDone3 = g_ev[16];
#define REC(e, st) do { if (ok) cudaEventRecord(e, st); } while (0)
#define WAIT(st, e) do { if (ok) cudaStreamWaitEvent(st, e, 0); } while (0)

    const dim3 gH(2, 79);
    const int TPB = 256;
    const int* rp1 = prp;
    const int* rp2 = prp + (N_NODES + 1);
    const int* cs1 = pcols;
    const int* cs2 = pcols + E_EDGES;
    const float* vl1 = pvals;
    const float* vl2 = pvals + E_EDGES;

    // ---- s0 head: rna operand ----
    REC(eFork, 0);
    fw_softmax<<<1, 32>>>(fW_rna, fW_atac, pfw);
    conv_a<<<cgrid((long long)N_NODES * D_RNA / 2, TPB), TPB>>>(X_rna, pacr, N_NODES, D_RNA, 6016);
    pad_a<<<cgrid((long long)N_NODES * 16, TPB), TPB>>>(pacr, N_NODES, 6016, 6000);
    REC(eAr, 0);

    // ---- s2: CSR build (nothing in front of it) ----
    WAIT(s2, eFork);
    for (int o = 0; o < 2; o++) {
        const int* rw = o ? row2 : row1;
        const int* cl = o ? col2 : col1;
        const float* vl = o ? val2 : val1;
        zero_cnt<<<40, 256, 0, s2>>>(pcnt + o * N_NODES);
        hist_rows<<<1250, 256, 0, s2>>>(rw, pcnt + o * N_NODES);
        exscan<<<1, 256, 0, s2>>>(pcnt + o * N_NODES, prp + o * (N_NODES + 1));
        copy_cur<<<40, 256, 0, s2>>>(prp + o * (N_NODES + 1), pcur + o * N_NODES);
        scatter_csr<<<1250, 256, 0, s2>>>(rw, cl, vl, pcur + o * N_NODES,
                                          pcols + o * E_EDGES, pvals + o * E_EDGES);
    }
    REC(eCsr, s2);

    // ---- s3: Wi_rna0 conversion first, then atac pipeline + weight convs --
    WAIT(s3, eFork);
    conv_b<<<cgrid((long long)D_RNA * HID / 2, TPB), TPB, 0, s3>>>(Wi_rna, pwir0, D_RNA, HID);
    pad_b<<<cgrid(16LL * HID, TPB), TPB, 0, s3>>>(pwir0 + (size_t)6000 * HID, 16 * HID);
    REC(eBw0, s3);
    conv_a<<<cgrid((long long)N_NODES * D_ATAC / 2, TPB), TPB, 0, s3>>>(
        X_atac, paca, N_NODES, D_ATAC, 15008);
    pad_a<<<cgrid((long long)N_NODES * 8, TPB), TPB, 0, s3>>>(paca, N_NODES, 15008, 15000);
    conv_b<<<cgrid((long long)D_ATAC * HID / 2, TPB), TPB, 0, s3>>>(Wi_atac, pwia0, D_ATAC, HID);
    pad_b<<<cgrid(8LL * HID, TPB), TPB, 0, s3>>>(pwia0 + (size_t)15000 * HID, 8 * HID);
    gemm_bf16<<<gH, 256, 0, s3>>>(paca, pwia0, bi_atac, pb3, N_NODES, HID, 15008, 0, 0);
    REC(eGa0, s3);
    conv_b<<<cgrid((long long)D_ATAC * HID / 2, TPB), TPB, 0, s3>>>(
        Wi_atac + (size_t)D_ATAC * HID, pwia1, D_ATAC, HID);
    pad_b<<<cgrid(8LL * HID, TPB), TPB, 0, s3>>>(pwia1 + (size_t)15000 * HID, 8 * HID);
    gemm_bf16<<<gH, 256, 0, s3>>>(paca, pwia1, bi_atac + HID, pb4, N_NODES, HID, 15008, 0, 0);
    REC(eGa1, s3);
    conv_b<<<cgrid(512LL * HID / 2, TPB), TPB, 0, s3>>>(Wo_rna, pwor, 512, HID);
    conv_b<<<cgrid(512LL * HID / 2, TPB), TPB, 0, s3>>>(Wo_atac, pwoa, 512, HID);
    conv_b<<<cgrid((long long)HID * HID / 2, TPB), TPB, 0, s3>>>(Wd1_rna, pd1r, HID, HID);
    conv_b<<<cgrid((long long)HID * HID / 2, TPB), TPB, 0, s3>>>(Wd1_atac, pd1a, HID, HID);
    conv_b<<<cgrid((long long)HID * D_RNA / 2, TPB), TPB, 0, s3>>>(Wd2_rna, pd2r, HID, D_RNA);
    conv_b<<<cgrid((long long)HID * D_ATAC / 2, TPB), TPB, 0, s3>>>(Wd2_atac, pd2a, HID, D_ATAC);
    REC(eWcv, s3);

    // ---- s0: G_rna0 ----
    WAIT(0, eBw0);
    gemm_bf16<<<gH, 256>>>(pacr, pwir0, bi_rna, pb0, N_NODES, HID, 6016, 0, 0);

    // ---- s2: G_rna1 + R1 hops ----
    WAIT(s2, eAr);
    conv_b<<<cgrid((long long)D_RNA * HID / 2, TPB), TPB, 0, s2>>>(
        Wi_rna + (size_t)D_RNA * HID, pwir1, D_RNA, HID);
    pad_b<<<cgrid(16LL * HID, TPB), TPB, 0, s2>>>(pwir1 + (size_t)6000 * HID, 16 * HID);
    gemm_bf16<<<gH, 256, 0, s2>>>(pacr, pwir1, bi_rna + HID, pb2, N_NODES, HID, 6016, 0, 0);
    {
        const float* wrow = pfw + (K_HOPS + 1);
        float* bufs[2] = {pb2, pb5};
        for (int k = 1; k <= K_HOPS; k++)
            spmm_fused<<<1250, 256, 0, s2>>>(rp2, cs2, vl2,
                                             bufs[(k + 1) & 1], bufs[k & 1],
                                             pzr + HID, wrow + k,
                                             (k == 1) ? wrow : (const float*)0,
                                             (k < K_HOPS) ? 1 : 0);
    }
    REC(eR1, s2);

    // ---- s0: R0 hops + A0 hops ----
    WAIT(0, eCsr);
    {
        const float* wrow = pfw;
        float* bufs[2] = {pb0, pb1};
        for (int k = 1; k <= K_HOPS; k++)
            spmm_fused<<<1250, 256>>>(rp1, cs1, vl1,
                                      bufs[(k + 1) & 1], bufs[k & 1], pzr, wrow + k,
                                      (k == 1) ? wrow : (const float*)0,
                                      (k < K_HOPS) ? 1 : 0);
    }
    REC(eR0, 0);
    WAIT(0, eGa0);
    {
        const float* wrow = pfw + 2 * (K_HOPS + 1);
        float* bufs[2] = {pb3, pb1};
        for (int k = 1; k <= K_HOPS; k++)
            spmm_fused<<<1250, 256>>>(rp1, cs1, vl1,
                                      bufs[(k + 1) & 1], bufs[k & 1], pza, wrow + k,
                                      (k == 1) ? wrow : (const float*)0,
                                      (k < K_HOPS) ? 1 : 0);
    }

    // ---- s2: A1 hops ----
    WAIT(s2, eGa1);
    {
        const float* wrow = pfw + 3 * (K_HOPS + 1);
        float* bufs[2] = {pb4, pb2};
        for (int k = 1; k <= K_HOPS; k++)
            spmm_fused<<<1250, 256, 0, s2>>>(rp2, cs2, vl2,
                                             bufs[(k + 1) & 1], bufs[k & 1],
                                             pza + HID, wrow + k,
                                             (k == 1) ? wrow : (const float*)0,
                                             (k < K_HOPS) ? 1 : 0);
    }
    REC(eA1, s2);

    // ---- s3: Wo_rna under atac hops ----
    WAIT(s3, eR0);
    WAIT(s3, eR1);
    conv_a<<<cgrid((long long)N_NODES * 512 / 2, TPB), TPB, 0, s3>>>(pzr, pawor, N_NODES, 512, 1536);
    gemm_bf16<<<gH, 256, 0, s3>>>(pawor, pwor, bo_rna, out_zrna, N_NODES, HID, 1536, 0, 0);
    REC(eWoR, s3);

    // ---- s0: Wo_atac (tile 0) ----
    WAIT(0, eA1);
    WAIT(0, eWcv);
    conv_a<<<cgrid((long long)N_NODES * 512 / 2, TPB), TPB>>>(pza, pawoa, N_NODES, 512, 1536);
    REC(eWoaC, 0);
    gemm_bf16<<<dim3(1, 79), 256>>>(pawoa, pwoa, bo_atac, out_zatac, N_NODES, HID, 1536, 0, 0);

    // ---- s3: Wo_atac (tile 1) ----
    WAIT(s3, eWoaC);
    gemm_bf16<<<dim3(1, 79), 256, 0, s3>>>(pawoa, pwoa, bo_atac, out_zatac,
                                           N_NODES, HID, 1536, 0, 1);
    REC(eWoa1, s3);

    // ---- s0: attention + fused z conversion ----
    WAIT(0, eWoR);
    WAIT(0, eWoa1);
    att_fuse_cv<<<1250, 256>>>(out_zrna, out_zatac, Wa, ba, out_z, out_w, paz);
    REC(eAtt, 0);

    // ---- s2: rna decoder ----
    WAIT(s2, eAtt);
    WAIT(s2, eWcv);
    gemm_bf16<<<gH, 256, 0, s2>>>(paz, pd1r, bd1_rna, pb2, N_NODES, HID, 768, 1, 0);
    conv_a<<<cgrid((long long)N_NODES * HID / 2, TPB), TPB, 0, s2>>>(pb2, padr, N_NODES, HID, 768);
    gemm_bf16<<<dim3(16, 79), 256, 0, s2>>>(padr, pd2r, bd2_rna, out_rrec,
                                            N_NODES, D_RNA, 768, 0, 0);

    // ---- s0: atac decoder layer 1 + first slice of d2 ----
    gemm_bf16<<<gH, 256>>>(paz, pd1a, bd1_atac, pb3, N_NODES, HID, 768, 1, 0);
    conv_a<<<cgrid((long long)N_NODES * HID / 2, TPB), TPB>>>(pb3, pada, N_NODES, HID, 768);
    REC(eAda, 0);
    gemm_bf16<<<dim3(14, 79), 256>>>(pada, pd2a, bd2_atac, out_arec,
                                     N_NODES, D_ATAC, 768, 0, 0);

    // ---- s2: second slice of atac d2 ----
    WAIT(s2, eAda);
    gemm_bf16<<<dim3(13, 79), 256, 0, s2>>>(pada, pd2a, bd2_atac, out_arec,
                                            N_NODES, D_ATAC, 768, 0, 14);
    REC(eDone2, s2);

    // ---- s3: third slice of atac d2 ----
    WAIT(s3, eAda);
    gemm_bf16<<<dim3(13, 79), 256, 0, s3>>>(pada, pd2a, bd2_atac, out_arec,
                                            N_NODES, D_ATAC, 768, 0, 27);
    REC(eDone3, s3);

    WAIT(0, eDone2);
    WAIT(0, eDone3);
#undef REC
#undef WAIT
}

// round 17
// speedup vs baseline: 1.0412x; 1.0002x over previous
#include <cuda_runtime.h>
#include <cuda_bf16.h>
#include <cstdint>

#define N_NODES 10000
#define E_EDGES 320000
#define HID 256
#define K_HOPS 10
#define D_RNA 2000
#define D_ATAC 5000

// ---------------- scratch (static device allocations; no cudaMalloc) -------
__device__ float g_b0[N_NODES * HID];
__device__ float g_b1[N_NODES * HID];
__device__ float g_b2[N_NODES * HID];
__device__ float g_b3[N_NODES * HID];
__device__ float g_b4[N_NODES * HID];
__device__ float g_b5[N_NODES * HID];
__device__ float g_zcr[N_NODES * 2 * HID];
__device__ float g_zca[N_NODES * 2 * HID];
__device__ float g_fw[4 * (K_HOPS + 1)];
__device__ int   g_rowptr[2 * (N_NODES + 1)];
__device__ int   g_cols[2 * E_EDGES];
__device__ float g_vals[2 * E_EDGES];
__device__ int   g_cnt[2 * N_NODES];
__device__ int   g_cur[2 * N_NODES];
// split-bf16 operand buffers
__device__ __nv_bfloat16 g_acr[(size_t)N_NODES * 6016];
__device__ __nv_bfloat16 g_aca[(size_t)N_NODES * 15008];
__device__ __nv_bfloat16 g_awor[(size_t)N_NODES * 1536];
__device__ __nv_bfloat16 g_awoa[(size_t)N_NODES * 1536];
__device__ __nv_bfloat16 g_az[(size_t)N_NODES * 768];
__device__ __nv_bfloat16 g_adr[(size_t)N_NODES * 768];
__device__ __nv_bfloat16 g_ada[(size_t)N_NODES * 768];
__device__ __nv_bfloat16 g_bwir0[6016 * 256];
__device__ __nv_bfloat16 g_bwir1[6016 * 256];
__device__ __nv_bfloat16 g_bwia0[15008 * 256];
__device__ __nv_bfloat16 g_bwia1[15008 * 256];
__device__ __nv_bfloat16 g_bwor[1536 * 256];
__device__ __nv_bfloat16 g_bwoa[1536 * 256];
__device__ __nv_bfloat16 g_bd1r[768 * 256];
__device__ __nv_bfloat16 g_bd1a[768 * 256];
__device__ __nv_bfloat16 g_bd2r[768 * 2000];
__device__ __nv_bfloat16 g_bd2a[768 * 5000];

// ================= split-bf16 conversion kernels ===========================
__global__ void conv_a(const float* __restrict__ A, __nv_bfloat16* __restrict__ out,
                       int M, int K, int Kcp)
{
    int kh = K >> 1;
    int total = M * kh;
    for (int i = blockIdx.x * blockDim.x + threadIdx.x; i < total;
         i += gridDim.x * blockDim.x) {
        int m = i / kh;
        int k = (i - m * kh) * 2;
        float2 x = *(const float2*)(A + (size_t)m * K + k);
        __nv_bfloat16 h0 = __float2bfloat16(x.x);
        __nv_bfloat16 h1 = __float2bfloat16(x.y);
        __nv_bfloat16 l0 = __float2bfloat16(x.x - __bfloat162float(h0));
        __nv_bfloat16 l1 = __float2bfloat16(x.y - __bfloat162float(h1));
        __nv_bfloat162 hp; hp.x = h0; hp.y = h1;
        __nv_bfloat162 lp; lp.x = l0; lp.y = l1;
        size_t base = (size_t)m * Kcp + k;
        *(__nv_bfloat162*)(out + base) = hp;
        *(__nv_bfloat162*)(out + base + K) = lp;
        *(__nv_bfloat162*)(out + base + 2 * K) = hp;
    }
}

__global__ void pad_a(__nv_bfloat16* out, int M, int Kcp, int start)
{
    int w = Kcp - start;
    int total = M * w;
    for (int i = blockIdx.x * blockDim.x + threadIdx.x; i < total;
         i += gridDim.x * blockDim.x) {
        int m = i / w;
        int j = i - m * w;
        out[(size_t)m * Kcp + start + j] = __float2bfloat16(0.f);
    }
}

__global__ void conv_b(const float* __restrict__ B, __nv_bfloat16* __restrict__ out,
                       int K, int N)
{
    int nh = N >> 1;
    int total = K * nh;
    for (int i = blockIdx.x * blockDim.x + threadIdx.x; i < total;
         i += gridDim.x * blockDim.x) {
        int k = i / nh;
        int n = (i - k * nh) * 2;
        float2 x = *(const float2*)(B + (size_t)k * N + n);
        __nv_bfloat16 h0 = __float2bfloat16(x.x);
        __nv_bfloat16 h1 = __float2bfloat16(x.y);
        __nv_bfloat16 l0 = __float2bfloat16(x.x - __bfloat162float(h0));
        __nv_bfloat16 l1 = __float2bfloat16(x.y - __bfloat162float(h1));
        __nv_bfloat162 hp; hp.x = h0; hp.y = h1;
        __nv_bfloat162 lp; lp.x = l0; lp.y = l1;
        *(__nv_bfloat162*)(out + (size_t)k * N + n) = hp;
        *(__nv_bfloat162*)(out + (size_t)(K + k) * N + n) = hp;
        *(__nv_bfloat162*)(out + (size_t)(2 * K + k) * N + n) = lp;
    }
}

__global__ void pad_b(__nv_bfloat16* out, int count)
{
    for (int i = blockIdx.x * blockDim.x + threadIdx.x; i < count;
         i += gridDim.x * blockDim.x)
        out[i] = __float2bfloat16(0.f);
}

// ================= bf16 tensor-core GEMM ===================================
__device__ __forceinline__ void cpa16(void* sm, const void* gm, bool p)
{
    unsigned int s = (unsigned int)__cvta_generic_to_shared(sm);
    int sz = p ? 16 : 0;
    asm volatile("cp.async.cg.shared.global [%0], [%1], 16, %2;"
                 :: "r"(s), "l"(gm), "r"(sz) : "memory");
}
__device__ __forceinline__ void ldsm4(unsigned int* d, const void* p)
{
    unsigned int s = (unsigned int)__cvta_generic_to_shared(p);
    asm volatile("ldmatrix.sync.aligned.m8n8.x4.shared.b16 {%0,%1,%2,%3}, [%4];"
                 : "=r"(d[0]), "=r"(d[1]), "=r"(d[2]), "=r"(d[3]) : "r"(s));
}
__device__ __forceinline__ void ldsm4t(unsigned int* d, const void* p)
{
    unsigned int s = (unsigned int)__cvta_generic_to_shared(p);
    asm volatile("ldmatrix.sync.aligned.m8n8.x4.trans.shared.b16 {%0,%1,%2,%3}, [%4];"
                 : "=r"(d[0]), "=r"(d[1]), "=r"(d[2]), "=r"(d[3]) : "r"(s));
}
__device__ __forceinline__ void mma16816(float* c, const unsigned int* a,
                                         unsigned int b0, unsigned int b1)
{
    asm volatile("mma.sync.aligned.m16n8k16.row.col.f32.bf16.bf16.f32 "
                 "{%0,%1,%2,%3}, {%4,%5,%6,%7}, {%8,%9}, {%0,%1,%2,%3};"
                 : "+f"(c[0]), "+f"(c[1]), "+f"(c[2]), "+f"(c[3])
                 : "r"(a[0]), "r"(a[1]), "r"(a[2]), "r"(a[3]), "r"(b0), "r"(b1));
}

__global__ __launch_bounds__(256, 2) void gemm_bf16(
    const __nv_bfloat16* __restrict__ A, const __nv_bfloat16* __restrict__ B,
    const float* __restrict__ bias, float* __restrict__ C,
    int M, int N, int Kc, int relu, int colBase)
{
    __shared__ __nv_bfloat16 As[2][128][40];
    __shared__ __nv_bfloat16 Bs[2][32][136];

    const int tid = threadIdx.x;
    const int lane = tid & 31;
    const int warp = tid >> 5;
    const int wm = warp >> 2;
    const int wn = warp & 3;
    const int row0 = blockIdx.y * 128;
    const int col0 = (blockIdx.x + colBase) * 128;

    const int ar = tid >> 1;
    const int ac = (tid & 1) << 4;
    const int arow = row0 + ar;
    const bool apred = arow < M;
    const __nv_bfloat16* Abase = A + (size_t)(apred ? arow : 0) * Kc + ac;

    const int br = tid >> 3;
    const int bc = (tid & 7) << 4;
    const int bcol = col0 + bc;
    const bool bp0 = bcol < N;
    const bool bp1 = (bcol + 8) < N;
    const int bc0 = bp0 ? bcol : 0;
    const int bc1 = bp1 ? (bcol + 8) : 0;

    float acc[4][4][4];
#pragma unroll
    for (int i = 0; i < 4; i++) {
#pragma unroll
        for (int j = 0; j < 4; j++) {
#pragma unroll
            for (int q = 0; q < 4; q++) acc[i][j][q] = 0.f;
        }
    }

    const int iters = Kc >> 5;

    cpa16(&As[0][ar][ac], Abase, apred);
    cpa16(&As[0][ar][ac + 8], Abase + 8, apred);
    {
        const __nv_bfloat16* Bb = B + (size_t)br * N;
        cpa16(&Bs[0][br][bc], Bb + bc0, bp0);
        cpa16(&Bs[0][br][bc + 8], Bb + bc1, bp1);
    }
    asm volatile("cp.async.commit_group;" ::: "memory");

    int s = 0;
    for (int it = 0; it < iters; it++) {
        if (it + 1 < iters) {
            const int kk = (it + 1) << 5;
            cpa16(&As[s ^ 1][ar][ac], Abase + kk, apred);
            cpa16(&As[s ^ 1][ar][ac + 8], Abase + kk + 8, apred);
            const __nv_bfloat16* Bb = B + (size_t)(kk + br) * N;
            cpa16(&Bs[s ^ 1][br][bc], Bb + bc0, bp0);
            cpa16(&Bs[s ^ 1][br][bc + 8], Bb + bc1, bp1);
            asm volatile("cp.async.commit_group;" ::: "memory");
            asm volatile("cp.async.wait_group 1;" ::: "memory");
        } else {
            asm volatile("cp.async.wait_group 0;" ::: "memory");
        }
        __syncthreads();

#pragma unroll
        for (int k16 = 0; k16 < 2; k16++) {
            unsigned int af[4][4];
#pragma unroll
            for (int mi = 0; mi < 4; mi++) {
                ldsm4(af[mi], &As[s][wm * 64 + mi * 16 + (lane & 15)]
                                    [k16 * 16 + ((lane >> 4) << 3)]);
            }
            unsigned int bfr[2][4];
#pragma unroll
            for (int g = 0; g < 2; g++) {
                ldsm4t(bfr[g], &Bs[s][k16 * 16 + (lane & 15)]
                                     [wn * 32 + g * 16 + ((lane >> 4) << 3)]);
            }
#pragma unroll
            for (int mi = 0; mi < 4; mi++) {
#pragma unroll
                for (int ni = 0; ni < 4; ni++) {
                    mma16816(acc[mi][ni], af[mi],
                             bfr[ni >> 1][(ni & 1) * 2],
                             bfr[ni >> 1][(ni & 1) * 2 + 1]);
                }
            }
        }
        __syncthreads();
        s ^= 1;
    }

#pragma unroll
    for (int mi = 0; mi < 4; mi++) {
        int r = row0 + wm * 64 + mi * 16 + (lane >> 2);
#pragma unroll
        for (int ni = 0; ni < 4; ni++) {
            int c = col0 + wn * 32 + ni * 8 + ((lane & 3) << 1);
            if (c < N) {
                float b0 = bias[c];
                float b1 = bias[c + 1];
                if (r < M) {
                    float o0 = acc[mi][ni][0] + b0;
                    float o1 = acc[mi][ni][1] + b1;
                    if (relu) { o0 = fmaxf(o0, 0.f); o1 = fmaxf(o1, 0.f); }
                    *(float2*)(C + (size_t)r * N + c) = make_float2(o0, o1);
                }
                if (r + 8 < M) {
                    float o2 = acc[mi][ni][2] + b0;
                    float o3 = acc[mi][ni][3] + b1;
                    if (relu) { o2 = fmaxf(o2, 0.f); o3 = fmaxf(o3, 0.f); }
                    *(float2*)(C + (size_t)(r + 8) * N + c) = make_float2(o2, o3);
                }
            }
        }
    }
}

// ================= CSR construction ========================================
__global__ void zero_cnt(int* cnt)
{
    int i = blockIdx.x * blockDim.x + threadIdx.x;
    if (i < N_NODES) cnt[i] = 0;
}
__global__ void hist_rows(const int* __restrict__ row, int* cnt)
{
    int i = blockIdx.x * blockDim.x + threadIdx.x;
    if (i < E_EDGES) atomicAdd(&cnt[row[i]], 1);
}
__global__ void exscan(const int* __restrict__ cnt, int* rowptr)
{
    __shared__ int part[256];
    int t = threadIdx.x;
    int base = t * 40;
    int s = 0;
#pragma unroll
    for (int j = 0; j < 40; j++) {
        int idx = base + j;
        if (idx < N_NODES) s += cnt[idx];
    }
    part[t] = s;
    __syncthreads();
    for (int off = 1; off < 256; off <<= 1) {
        int v = (t >= off) ? part[t - off] : 0;
        __syncthreads();
        part[t] += v;
        __syncthreads();
    }
    int run = (t > 0) ? part[t - 1] : 0;
#pragma unroll
    for (int j = 0; j < 40; j++) {
        int idx = base + j;
        if (idx < N_NODES) { rowptr[idx] = run; run += cnt[idx]; }
    }
    if (t == 255) rowptr[N_NODES] = part[255];
}
__global__ void copy_cur(const int* __restrict__ rowptr, int* cur)
{
    int i = blockIdx.x * blockDim.x + threadIdx.x;
    if (i < N_NODES) cur[i] = rowptr[i];
}
__global__ void scatter_csr(const int* __restrict__ row, const int* __restrict__ col,
                            const float* __restrict__ val, int* cur,
                            int* __restrict__ oc, float* __restrict__ ov)
{
    int i = blockIdx.x * blockDim.x + threadIdx.x;
    if (i < E_EDGES) {
        int r = row[i];
        int p = atomicAdd(&cur[r], 1);
        oc[p] = col[i];
        ov[p] = val[i];
    }
}

// ================= fW softmax ==============================================
__global__ void fw_softmax(const float* __restrict__ fw_rna,
                           const float* __restrict__ fw_atac, float* out)
{
    int t = threadIdx.x;
    if (t >= 4) return;
    const float* src = (t < 2) ? (fw_rna + t * (K_HOPS + 1))
                               : (fw_atac + (t - 2) * (K_HOPS + 1));
    float m = -1e30f;
    for (int k = 0; k <= K_HOPS; k++) m = fmaxf(m, src[k]);
    float e[K_HOPS + 1];
    float s = 0.f;
    for (int k = 0; k <= K_HOPS; k++) { e[k] = expf(src[k] - m); s += e[k]; }
    float inv = 1.f / s;
    for (int k = 0; k <= K_HOPS; k++) out[t * (K_HOPS + 1) + k] = e[k] * inv;
}

// ================= propagation =============================================
// Fused hop, edge loop unrolled x4 for deeper MLP. Accumulation remains
// STRICTLY sequential in edge order (bit-identical result to the x2 version).
// If w0p != null (first hop): acc = w0*x[row] + w*s; else acc += w*s.
// If wx==0 the xout store is skipped (final hop, dead value).
__global__ __launch_bounds__(256) void spmm_fused(
    const int* __restrict__ rowptr, const int* __restrict__ cols,
    const float* __restrict__ vals, const float* __restrict__ x,
    float* __restrict__ xout, float* __restrict__ acc,
    const float* __restrict__ wp, const float* __restrict__ w0p, int wx)
{
    int r = blockIdx.x * 8 + (threadIdx.x >> 5);
    if (r >= N_NODES) return;
    int lane = threadIdx.x & 31;
    float w = wp[0];
    int e0 = rowptr[r];
    int e1 = rowptr[r + 1];

    float4 s0 = make_float4(0.f, 0.f, 0.f, 0.f);
    float4 s1 = make_float4(0.f, 0.f, 0.f, 0.f);
    int e = e0;
    for (; e + 3 < e1; e += 4) {
        int c0 = cols[e];
        int c1 = cols[e + 1];
        int c2 = cols[e + 2];
        int c3 = cols[e + 3];
        float v0 = vals[e];
        float v1 = vals[e + 1];
        float v2 = vals[e + 2];
        float v3 = vals[e + 3];
        const float4* p0 = (const float4*)(x + (size_t)c0 * HID);
        const float4* p1 = (const float4*)(x + (size_t)c1 * HID);
        const float4* p2 = (const float4*)(x + (size_t)c2 * HID);
        const float4* p3 = (const float4*)(x + (size_t)c3 * HID);
        float4 a0 = p0[lane];
        float4 a1 = p0[lane + 32];
        float4 b0 = p1[lane];
        float4 b1 = p1[lane + 32];
        float4 d0 = p2[lane];
        float4 d1 = p2[lane + 32];
        float4 f0 = p3[lane];
        float4 f1 = p3[lane + 32];
        s0.x += v0 * a0.x; s0.y += v0 * a0.y; s0.z += v0 * a0.z; s0.w += v0 * a0.w;
        s1.x += v0 * a1.x; s1.y += v0 * a1.y; s1.z += v0 * a1.z; s1.w += v0 * a1.w;
        s0.x += v1 * b0.x; s0.y += v1 * b0.y; s0.z += v1 * b0.z; s0.w += v1 * b0.w;
        s1.x += v1 * b1.x; s1.y += v1 * b1.y; s1.z += v1 * b1.z; s1.w += v1 * b1.w;
        s0.x += v2 * d0.x; s0.y += v2 * d0.y; s0.z += v2 * d0.z; s0.w += v2 * d0.w;
        s1.x += v2 * d1.x; s1.y += v2 * d1.y; s1.z += v2 * d1.z; s1.w += v2 * d1.w;
        s0.x += v3 * f0.x; s0.y += v3 * f0.y; s0.z += v3 * f0.z; s0.w += v3 * f0.w;
        s1.x += v3 * f1.x; s1.y += v3 * f1.y; s1.z += v3 * f1.z; s1.w += v3 * f1.w;
    }
    for (; e < e1; e++) {
        int ca = cols[e];
        float va = vals[e];
        const float4* xa = (const float4*)(x + (size_t)ca * HID);
        float4 a0 = xa[lane];
        float4 a1 = xa[lane + 32];
        s0.x += va * a0.x; s0.y += va * a0.y; s0.z += va * a0.z; s0.w += va * a0.w;
        s1.x += va * a1.x; s1.y += va * a1.y; s1.z += va * a1.z; s1.w += va * a1.w;
    }

    if (wx) {
        float4* xo = (float4*)(xout + (size_t)r * HID);
        xo[lane] = s0;
        xo[lane + 32] = s1;
    }
    float4* ap = (float4*)(acc + (size_t)r * 512);
    if (w0p) {
        float w0 = w0p[0];
        const float4* xr = (const float4*)(x + (size_t)r * HID);
        float4 h0 = xr[lane];
        float4 h1 = xr[lane + 32];
        float4 q0, q1;
        q0.x = w0 * h0.x + w * s0.x; q0.y = w0 * h0.y + w * s0.y;
        q0.z = w0 * h0.z + w * s0.z; q0.w = w0 * h0.w + w * s0.w;
        q1.x = w0 * h1.x + w * s1.x; q1.y = w0 * h1.y + w * s1.y;
        q1.z = w0 * h1.z + w * s1.z; q1.w = w0 * h1.w + w * s1.w;
        ap[lane] = q0;
        ap[lane + 32] = q1;
    } else {
        float4 q0 = ap[lane];
        q0.x += w * s0.x; q0.y += w * s0.y; q0.z += w * s0.z; q0.w += w * s0.w;
        ap[lane] = q0;
        float4 q1 = ap[lane + 32];
        q1.x += w * s1.x; q1.y += w * s1.y; q1.z += w * s1.z; q1.w += w * s1.w;
        ap[lane + 32] = q1;
    }
}

// ================= attention fusion + z bf16-split conversion ==============
__global__ __launch_bounds__(256) void att_fuse_cv(
    const float* __restrict__ zr, const float* __restrict__ za,
    const float* __restrict__ Wa, const float* __restrict__ ba,
    float* __restrict__ z, float* __restrict__ wout,
    __nv_bfloat16* __restrict__ zcv)
{
    int r = blockIdx.x * 8 + (threadIdx.x >> 5);
    if (r >= N_NODES) return;
    int lane = threadIdx.x & 31;
    const float* zrr = zr + (long long)r * HID;
    const float* zar = za + (long long)r * HID;

    float p0 = 0.f;
    float p1 = 0.f;
    for (int c = lane; c < HID; c += 32) {
        float v = zrr[c];
        p0 += v * Wa[c * 2];
        p1 += v * Wa[c * 2 + 1];
        float u = zar[c];
        p0 += u * Wa[(HID + c) * 2];
        p1 += u * Wa[(HID + c) * 2 + 1];
    }
#pragma unroll
    for (int off = 16; off; off >>= 1) {
        p0 += __shfl_xor_sync(0xffffffffu, p0, off);
        p1 += __shfl_xor_sync(0xffffffffu, p1, off);
    }
    float l0 = p0 + ba[0];
    float l1 = p1 + ba[1];
    float m = fmaxf(l0, l1);
    float e0 = expf(l0 - m);
    float e1 = expf(l1 - m);
    float inv = 1.f / (e0 + e1);
    float w0 = e0 * inv;
    float w1 = e1 * inv;
    if (lane == 0) {
        wout[r * 2 + 0] = w0;
        wout[r * 2 + 1] = w1;
    }
    __nv_bfloat16* zc = zcv + (size_t)r * 768;
    for (int c = lane; c < HID; c += 32) {
        float zv = w0 * zrr[c] + w1 * zar[c];
        z[(long long)r * HID + c] = zv;
        __nv_bfloat16 hi = __float2bfloat16(zv);
        __nv_bfloat16 lo = __float2bfloat16(zv - __bfloat162float(hi));
        zc[c] = hi;
        zc[c + 256] = lo;
        zc[c + 512] = hi;
    }
}

// ================= host orchestration ======================================
static inline int cgrid(long long total, int tpb)
{
    long long b = (total + tpb - 1) / tpb;
    if (b > 65535) b = 65535;
    return (int)b;
}

// Streams/events created once on the FIRST call (before the harness's
// pre-capture baseline) and cached; the capture call allocates nothing.
static cudaStream_t g_s2 = 0;
static cudaStream_t g_s3 = 0;
static cudaEvent_t  g_ev[17];
static int          g_res_state = 0;

extern "C" void kernel_launch(void* const* d_in, const int* in_sizes, int n_in,
                              void* d_out, int out_size)
{
    const float* X_rna  = (const float*)d_in[0];
    const float* X_atac = (const float*)d_in[1];
    const int*   row1 = (const int*)d_in[2];
    const int*   col1 = (const int*)d_in[3];
    const float* val1 = (const float*)d_in[4];
    const int*   row2 = (const int*)d_in[5];
    const int*   col2 = (const int*)d_in[6];
    const float* val2 = (const float*)d_in[7];
    const float* Wi_rna  = (const float*)d_in[8];
    const float* bi_rna  = (const float*)d_in[9];
    const float* fW_rna  = (const float*)d_in[10];
    const float* Wo_rna  = (const float*)d_in[11];
    const float* bo_rna  = (const float*)d_in[12];
    const float* Wi_atac = (const float*)d_in[13];
    const float* bi_atac = (const float*)d_in[14];
    const float* fW_atac = (const float*)d_in[15];
    const float* Wo_atac = (const float*)d_in[16];
    const float* bo_atac = (const float*)d_in[17];
    const float* Wa = (const float*)d_in[18];
    const float* ba = (const float*)d_in[19];
    const float* Wd1_rna  = (const float*)d_in[20];
    const float* bd1_rna  = (const float*)d_in[21];
    const float* Wd2_rna  = (const float*)d_in[22];
    const float* bd2_rna  = (const float*)d_in[23];
    const float* Wd1_atac = (const float*)d_in[24];
    const float* bd1_atac = (const float*)d_in[25];
    const float* Wd2_atac = (const float*)d_in[26];
    const float* bd2_atac = (const float*)d_in[27];

    float* out = (float*)d_out;
    float* out_z     = out;
    float* out_zrna  = out + (size_t)N_NODES * HID;
    float* out_zatac = out + 2 * (size_t)N_NODES * HID;
    float* out_w     = out + 3 * (size_t)N_NODES * HID;
    float* out_rrec  = out_w + (size_t)N_NODES * 2;
    float* out_arec  = out_rrec + (size_t)N_NODES * D_RNA;

    float *pb0 = 0, *pb1 = 0, *pb2 = 0, *pb3 = 0, *pb4 = 0, *pb5 = 0;
    float *pzr = 0, *pza = 0, *pfw = 0, *pvals = 0;
    int *prp = 0, *pcols = 0, *pcnt = 0, *pcur = 0;
    __nv_bfloat16 *pacr = 0, *paca = 0, *pawor = 0, *pawoa = 0;
    __nv_bfloat16 *paz = 0, *padr = 0, *pada = 0;
    __nv_bfloat16 *pwir0 = 0, *pwir1 = 0, *pwia0 = 0, *pwia1 = 0;
    __nv_bfloat16 *pwor = 0, *pwoa = 0, *pd1r = 0, *pd1a = 0, *pd2r = 0, *pd2a = 0;
    cudaGetSymbolAddress((void**)&pb0, g_b0);
    cudaGetSymbolAddress((void**)&pb1, g_b1);
    cudaGetSymbolAddress((void**)&pb2, g_b2);
    cudaGetSymbolAddress((void**)&pb3, g_b3);
    cudaGetSymbolAddress((void**)&pb4, g_b4);
    cudaGetSymbolAddress((void**)&pb5, g_b5);
    cudaGetSymbolAddress((void**)&pzr, g_zcr);
    cudaGetSymbolAddress((void**)&pza, g_zca);
    cudaGetSymbolAddress((void**)&pfw, g_fw);
    cudaGetSymbolAddress((void**)&prp, g_rowptr);
    cudaGetSymbolAddress((void**)&pcols, g_cols);
    cudaGetSymbolAddress((void**)&pvals, g_vals);
    cudaGetSymbolAddress((void**)&pcnt, g_cnt);
    cudaGetSymbolAddress((void**)&pcur, g_cur);
    cudaGetSymbolAddress((void**)&pacr, g_acr);
    cudaGetSymbolAddress((void**)&paca, g_aca);
    cudaGetSymbolAddress((void**)&pawor, g_awor);
    cudaGetSymbolAddress((void**)&pawoa, g_awoa);
    cudaGetSymbolAddress((void**)&paz, g_az);
    cudaGetSymbolAddress((void**)&padr, g_adr);
    cudaGetSymbolAddress((void**)&pada, g_ada);
    cudaGetSymbolAddress((void**)&pwir0, g_bwir0);
    cudaGetSymbolAddress((void**)&pwir1, g_bwir1);
    cudaGetSymbolAddress((void**)&pwia0, g_bwia0);
    cudaGetSymbolAddress((void**)&pwia1, g_bwia1);
    cudaGetSymbolAddress((void**)&pwor, g_bwor);
    cudaGetSymbolAddress((void**)&pwoa, g_bwoa);
    cudaGetSymbolAddress((void**)&pd1r, g_bd1r);
    cudaGetSymbolAddress((void**)&pd1a, g_bd1a);
    cudaGetSymbolAddress((void**)&pd2r, g_bd2r);
    cudaGetSymbolAddress((void**)&pd2a, g_bd2a);

    if (g_res_state == 0) {
        bool created = true;
        for (int i = 0; i < 17; i++) {
            if (created &&
                cudaEventCreateWithFlags(&g_ev[i], cudaEventDisableTiming) != cudaSuccess)
                created = false;
        }
        if (created &&
            cudaStreamCreateWithFlags(&g_s2, cudaStreamNonBlocking) != cudaSuccess)
            created = false;
        if (created &&
            cudaStreamCreateWithFlags(&g_s3, cudaStreamNonBlocking) != cudaSuccess)
            created = false;
        g_res_state = created ? 1 : -1;
    }
    const bool ok = (g_res_state == 1);
    cudaStream_t s2 = ok ? g_s2 : 0;
    cudaStream_t s3 = ok ? g_s3 : 0;
    cudaEvent_t eFork = g_ev[0], eAr = g_ev[1], eBw0 = g_ev[2], eCsr1 = g_ev[3];
    cudaEvent_t eGa0 = g_ev[4], eGa1 = g_ev[5], eWcv = g_ev[6], eR0 = g_ev[7];
    cudaEvent_t eR1 = g_ev[8], eA1 = g_ev[9], eWoR = g_ev[10], eWoaC = g_ev[11];
    cudaEvent_t eWoa1 = g_ev[12], eAtt = g_ev[13], eAda = g_ev[14];
    cudaEvent_t eDone2 = g_ev[15], eDone3 = g_ev[16];
#define REC(e, st) do { if (ok) cudaEventRecord(e, st); } while (0)
#define WAIT(st, e) do { if (ok) cudaStreamWaitEvent(st, e, 0); } while (0)

    const dim3 gH(2, 79);
    const int TPB = 256;
    const int* rp1 = prp;
    const int* rp2 = prp + (N_NODES + 1);
    const int* cs1 = pcols;
    const int* cs2 = pcols + E_EDGES;
    const float* vl1 = pvals;
    const float* vl2 = pvals + E_EDGES;

    // ---- s0 head: rna operand ----
    REC(eFork, 0);
    fw_softmax<<<1, 32>>>(fW_rna, fW_atac, pfw);
    conv_a<<<cgrid((long long)N_NODES * D_RNA / 2, TPB), TPB>>>(X_rna, pacr, N_NODES, D_RNA, 6016);
    pad_a<<<cgrid((long long)N_NODES * 16, TPB), TPB>>>(pacr, N_NODES, 6016, 6000);
    REC(eAr, 0);

    // ---- s2: CSR build. eCsr1 fires after GRAPH 1 only (R0's sole CSR dep);
    //      graph 2's build still precedes R1/A1 in s2 program order. ----
    WAIT(s2, eFork);
    for (int o = 0; o < 2; o++) {
        const int* rw = o ? row2 : row1;
        const int* cl = o ? col2 : col1;
        const float* vl = o ? val2 : val1;
        zero_cnt<<<40, 256, 0, s2>>>(pcnt + o * N_NODES);
        hist_rows<<<1250, 256, 0, s2>>>(rw, pcnt + o * N_NODES);
        exscan<<<1, 256, 0, s2>>>(pcnt + o * N_NODES, prp + o * (N_NODES + 1));
        copy_cur<<<40, 256, 0, s2>>>(prp + o * (N_NODES + 1), pcur + o * N_NODES);
        scatter_csr<<<1250, 256, 0, s2>>>(rw, cl, vl, pcur + o * N_NODES,
                                          pcols + o * E_EDGES, pvals + o * E_EDGES);
        if (o == 0) REC(eCsr1, s2);
    }

    // ---- s3: Wi_rna0 conversion first, then atac pipeline + weight convs --
    WAIT(s3, eFork);
    conv_b<<<cgrid((long long)D_RNA * HID / 2, TPB), TPB, 0, s3>>>(Wi_rna, pwir0, D_RNA, HID);
    pad_b<<<cgrid(16LL * HID, TPB), TPB, 0, s3>>>(pwir0 + (size_t)6000 * HID, 16 * HID);
    REC(eBw0, s3);
    conv_a<<<cgrid((long long)N_NODES * D_ATAC / 2, TPB), TPB, 0, s3>>>(
        X_atac, paca, N_NODES, D_ATAC, 15008);
    pad_a<<<cgrid((long long)N_NODES * 8, TPB), TPB, 0, s3>>>(paca, N_NODES, 15008, 15000);
    conv_b<<<cgrid((long long)D_ATAC * HID / 2, TPB), TPB, 0, s3>>>(Wi_atac, pwia0, D_ATAC, HID);
    pad_b<<<cgrid(8LL * HID, TPB), TPB, 0, s3>>>(pwia0 + (size_t)15000 * HID, 8 * HID);
    gemm_bf16<<<gH, 256, 0, s3>>>(paca, pwia0, bi_atac, pb3, N_NODES, HID, 15008, 0, 0);
    REC(eGa0, s3);
    conv_b<<<cgrid((long long)D_ATAC * HID / 2, TPB), TPB, 0, s3>>>(
        Wi_atac + (size_t)D_ATAC * HID, pwia1, D_ATAC, HID);
    pad_b<<<cgrid(8LL * HID, TPB), TPB, 0, s3>>>(pwia1 + (size_t)15000 * HID, 8 * HID);
    gemm_bf16<<<gH, 256, 0, s3>>>(paca, pwia1, bi_atac + HID, pb4, N_NODES, HID, 15008, 0, 0);
    REC(eGa1, s3);
    conv_b<<<cgrid(512LL * HID / 2, TPB), TPB, 0, s3>>>(Wo_rna, pwor, 512, HID);
    conv_b<<<cgrid(512LL * HID / 2, TPB), TPB, 0, s3>>>(Wo_atac, pwoa, 512, HID);
    conv_b<<<cgrid((long long)HID * HID / 2, TPB), TPB, 0, s3>>>(Wd1_rna, pd1r, HID, HID);
    conv_b<<<cgrid((long long)HID * HID / 2, TPB), TPB, 0, s3>>>(Wd1_atac, pd1a, HID, HID);
    conv_b<<<cgrid((long long)HID * D_RNA / 2, TPB), TPB, 0, s3>>>(Wd2_rna, pd2r, HID, D_RNA);
    conv_b<<<cgrid((long long)HID * D_ATAC / 2, TPB), TPB, 0, s3>>>(Wd2_atac, pd2a, HID, D_ATAC);
    REC(eWcv, s3);

    // ---- s0: G_rna0 ----
    WAIT(0, eBw0);
    gemm_bf16<<<gH, 256>>>(pacr, pwir0, bi_rna, pb0, N_NODES, HID, 6016, 0, 0);

    // ---- s2: G_rna1 + R1 hops ----
    WAIT(s2, eAr);
    conv_b<<<cgrid((long long)D_RNA * HID / 2, TPB), TPB, 0, s2>>>(
        Wi_rna + (size_t)D_RNA * HID, pwir1, D_RNA, HID);
    pad_b<<<cgrid(16LL * HID, TPB), TPB, 0, s2>>>(pwir1 + (size_t)6000 * HID, 16 * HID);
    gemm_bf16<<<gH, 256, 0, s2>>>(pacr, pwir1, bi_rna + HID, pb2, N_NODES, HID, 6016, 0, 0);
    {
        const float* wrow = pfw + (K_HOPS + 1);
        float* bufs[2] = {pb2, pb5};
        for (int k = 1; k <= K_HOPS; k++)
            spmm_fused<<<1250, 256, 0, s2>>>(rp2, cs2, vl2,
                                             bufs[(k + 1) & 1], bufs[k & 1],
                                             pzr + HID, wrow + k,
                                             (k == 1) ? wrow : (const float*)0,
                                             (k < K_HOPS) ? 1 : 0);
    }
    REC(eR1, s2);

    // ---- s0: R0 hops + A0 hops ----
    WAIT(0, eCsr1);
    {
        const float* wrow = pfw;
        float* bufs[2] = {pb0, pb1};
        for (int k = 1; k <= K_HOPS; k++)
            spmm_fused<<<1250, 256>>>(rp1, cs1, vl1,
                                      bufs[(k + 1) & 1], bufs[k & 1], pzr, wrow + k,
                                      (k == 1) ? wrow : (const float*)0,
                                      (k < K_HOPS) ? 1 : 0);
    }
    REC(eR0, 0);
    WAIT(0, eGa0);
    {
        const float* wrow = pfw + 2 * (K_HOPS + 1);
        float* bufs[2] = {pb3, pb1};
        for (int k = 1; k <= K_HOPS; k++)
            spmm_fused<<<1250, 256>>>(rp1, cs1, vl1,
                                      bufs[(k + 1) & 1], bufs[k & 1], pza, wrow + k,
                                      (k == 1) ? wrow : (const float*)0,
                                      (k < K_HOPS) ? 1 : 0);
    }

    // ---- s2: A1 hops ----
    WAIT(s2, eGa1);
    {
        const float* wrow = pfw + 3 * (K_HOPS + 1);
        float* bufs[2] = {pb4, pb2};
        for (int k = 1; k <= K_HOPS; k++)
            spmm_fused<<<1250, 256, 0, s2>>>(rp2, cs2, vl2,
                                             bufs[(k + 1) & 1], bufs[k & 1],
                                             pza + HID, wrow + k,
                                             (k == 1) ? wrow : (const float*)0,
                                             (k < K_HOPS) ? 1 : 0);
    }
    REC(eA1, s2);

    // ---- s3: Wo_rna under atac hops ----
    WAIT(s3, eR0);
    WAIT(s3, eR1);
    conv_a<<<cgrid((long long)N_NODES * 512 / 2, TPB), TPB, 0, s3>>>(pzr, pawor, N_NODES, 512, 1536);
    gemm_bf16<<<gH, 256, 0, s3>>>(pawor, pwor, bo_rna, out_zrna, N_NODES, HID, 1536, 0, 0);
    REC(eWoR, s3);

    // ---- s0: Wo_atac (tile 0) ----
    WAIT(0, eA1);
    WAIT(0, eWcv);
    conv_a<<<cgrid((long long)N_NODES * 512 / 2, TPB), TPB>>>(pza, pawoa, N_NODES, 512, 1536);
    REC(eWoaC, 0);
    gemm_bf16<<<dim3(1, 79), 256>>>(pawoa, pwoa, bo_atac, out_zatac, N_NODES, HID, 1536, 0, 0);

    // ---- s3: Wo_atac (tile 1) ----
    WAIT(s3, eWoaC);
    gemm_bf16<<<dim3(1, 79), 256, 0, s3>>>(pawoa, pwoa, bo_atac, out_zatac,
                                           N_NODES, HID, 1536, 0, 1);
    REC(eWoa1, s3);

    // ---- s0: attention + fused z conversion ----
    WAIT(0, eWoR);
    WAIT(0, eWoa1);
    att_fuse_cv<<<1250, 256>>>(out_zrna, out_zatac, Wa, ba, out_z, out_w, paz);
    REC(eAtt, 0);

    // ---- s2: rna decoder ----
    WAIT(s2, eAtt);
    WAIT(s2, eWcv);
    gemm_bf16<<<gH, 256, 0, s2>>>(paz, pd1r, bd1_rna, pb2, N_NODES, HID, 768, 1, 0);
    conv_a<<<cgrid((long long)N_NODES * HID / 2, TPB), TPB, 0, s2>>>(pb2, padr, N_NODES, HID, 768);
    gemm_bf16<<<dim3(16, 79), 256, 0, s2>>>(padr, pd2r, bd2_rna, out_rrec,
                                            N_NODES, D_RNA, 768, 0, 0);

    // ---- s0: atac decoder layer 1 + first slice of d2 ----
    gemm_bf16<<<gH, 256>>>(paz, pd1a, bd1_atac, pb3, N_NODES, HID, 768, 1, 0);
    conv_a<<<cgrid((long long)N_NODES * HID / 2, TPB), TPB>>>(pb3, pada, N_NODES, HID, 768);
    REC(eAda, 0);
    gemm_bf16<<<dim3(14, 79), 256>>>(pada, pd2a, bd2_atac, out_arec,
                                     N_NODES, D_ATAC, 768, 0, 0);

    // ---- s2: second slice of atac d2 ----
    WAIT(s2, eAda);
    gemm_bf16<<<dim3(13, 79), 256, 0, s2>>>(pada, pd2a, bd2_atac, out_arec,
                                            N_NODES, D_ATAC, 768, 0, 14);
    REC(eDone2, s2);

    // ---- s3: third slice of atac d2 ----
    WAIT(s3, eAda);
    gemm_bf16<<<dim3(13, 79), 256, 0, s3>>>(pada, pd2a, bd2_atac, out_arec,
                                            N_NODES, D_ATAC, 768, 0, 27);
    REC(eDone3, s3);

    WAIT(0, eDone2);
    WAIT(0, eDone3);
#undef REC
#undef WAIT
}